// round 9
// baseline (speedup 1.0000x reference)
#include <cuda_runtime.h>
#include <cuda_bf16.h>
#include <cuda_fp16.h>
#include <cstdint>

// ---------------- problem dims ----------------
#define PP 2
#define JJ 32
#define KK 32
#define MM 128
#define LL 16
#define NN 128
#define BATCH 512
#define KN 4096
#define JM 4096
#define BKC 64                 // GEMM K-chunk (fp16 elements)
#define NCHUNK (KN / BKC)      // 64
#define STAGE 32768            // bytes per pipeline stage (A 16KB + W 16KB)
#define NSTG 4

// ---------------- device scratch (no cudaMalloc allowed) ----------------
__device__ float g_pmax[256];
__device__ float g_pmin[256];
__device__ float g_scale;
__device__ unsigned g_cnt = 0;
__device__ __half g_q[(size_t)BATCH * KN];       // quantized activations (exact ints, fp16)
__device__ __half g_W[(size_t)JM * KN];          // fp16 weight matrix

// ---------------- PTX helpers (sm_100-safe only) ----------------
__device__ __forceinline__ uint32_t smem_u32(const void* p) {
    uint32_t a;
    asm("{ .reg .u64 t; cvta.to.shared.u64 t, %1; cvt.u32.u64 %0, t; }" : "=r"(a) : "l"(p));
    return a;
}

__device__ __forceinline__ void cp16(uint32_t dst, const void* src) {
    asm volatile("cp.async.cg.shared.global [%0], [%1], 16;\n" :: "r"(dst), "l"(src));
}
#define CP_COMMIT() asm volatile("cp.async.commit_group;\n" ::: "memory")
#define CP_WAIT(n)  asm volatile("cp.async.wait_group %0;\n" :: "n"(n) : "memory")

__device__ __forceinline__ void ldsm4(uint32_t* r, uint32_t addr) {
    asm volatile("ldmatrix.sync.aligned.m8n8.x4.shared.b16 {%0,%1,%2,%3}, [%4];"
        : "=r"(r[0]), "=r"(r[1]), "=r"(r[2]), "=r"(r[3]) : "r"(addr));
}
__device__ __forceinline__ void ldsm4t(uint32_t* r, uint32_t addr) {
    asm volatile("ldmatrix.sync.aligned.m8n8.x4.trans.shared.b16 {%0,%1,%2,%3}, [%4];"
        : "=r"(r[0]), "=r"(r[1]), "=r"(r[2]), "=r"(r[3]) : "r"(addr));
}

// bf16 MMA (used in buildw where operands are exact small integers)
__device__ __forceinline__ void mma16816_bf(float* c, const uint32_t* a, const uint32_t* b) {
    asm volatile(
        "mma.sync.aligned.m16n8k16.row.col.f32.bf16.bf16.f32 "
        "{%0,%1,%2,%3}, {%4,%5,%6,%7}, {%8,%9}, {%0,%1,%2,%3};"
        : "+f"(c[0]), "+f"(c[1]), "+f"(c[2]), "+f"(c[3])
        : "r"(a[0]), "r"(a[1]), "r"(a[2]), "r"(a[3]), "r"(b[0]), "r"(b[1]));
}
// fp16 MMA with fp32 accum (main GEMM)
__device__ __forceinline__ void mma16816_f16(float* c, const uint32_t* a, const uint32_t* b) {
    asm volatile(
        "mma.sync.aligned.m16n8k16.row.col.f32.f16.f16.f32 "
        "{%0,%1,%2,%3}, {%4,%5,%6,%7}, {%8,%9}, {%0,%1,%2,%3};"
        : "+f"(c[0]), "+f"(c[1]), "+f"(c[2]), "+f"(c[3])
        : "r"(a[0]), "r"(a[1]), "r"(a[2]), "r"(a[3]), "r"(b[0]), "r"(b[1]));
}

// ---------------- kernel 1: min/max partials + last-block finalize ----------------
__global__ void __launch_bounds__(256) k_minmax(const float* __restrict__ x, int n4) {
    const float4* x4 = (const float4*)x;
    float mx = -3.4e38f, mn = 3.4e38f;
    for (int i = blockIdx.x * blockDim.x + threadIdx.x; i < n4; i += gridDim.x * blockDim.x) {
        float4 v = x4[i];
        mx = fmaxf(mx, fmaxf(fmaxf(v.x, v.y), fmaxf(v.z, v.w)));
        mn = fminf(mn, fminf(fminf(v.x, v.y), fminf(v.z, v.w)));
    }
    __shared__ float smx[256], smn[256];
    __shared__ int s_last;
    int t = threadIdx.x;
    smx[t] = mx; smn[t] = mn;
    __syncthreads();
    for (int s = 128; s > 0; s >>= 1) {
        if (t < s) { smx[t] = fmaxf(smx[t], smx[t + s]); smn[t] = fminf(smn[t], smn[t + s]); }
        __syncthreads();
    }
    if (t == 0) {
        g_pmax[blockIdx.x] = smx[0];
        g_pmin[blockIdx.x] = smn[0];
        __threadfence();
        unsigned old = atomicAdd(&g_cnt, 1);
        s_last = (old == gridDim.x - 1);
    }
    __syncthreads();
    if (s_last) {
        __threadfence();
        smx[t] = g_pmax[t]; smn[t] = g_pmin[t];
        __syncthreads();
        for (int s = 128; s > 0; s >>= 1) {
            if (t < s) { smx[t] = fmaxf(smx[t], smx[t + s]); smn[t] = fminf(smn[t], smn[t + s]); }
            __syncthreads();
        }
        if (t == 0) {
            float s = __fdiv_rn(smx[0] - smn[0], 254.0f);   // (max-min)/(2*qmax), qmax=127
            g_scale = fmaxf(s, 1e-8f);
            g_cnt = 0;                                       // reset for graph replay
        }
    }
}

// ---------------- kernel 3: quantize activations to exact fp16 integers ----------------
__global__ void __launch_bounds__(256) k_quant(const float* __restrict__ x) {
    float s = g_scale;
    int i = blockIdx.x * blockDim.x + threadIdx.x;   // one float4 per thread
    const float4* x4 = (const float4*)x;
    float4 v = x4[i];
    float q0 = fminf(fmaxf(rintf(__fdiv_rn(v.x, s)), -127.f), 127.f);
    float q1 = fminf(fmaxf(rintf(__fdiv_rn(v.y, s)), -127.f), 127.f);
    float q2 = fminf(fmaxf(rintf(__fdiv_rn(v.z, s)), -127.f), 127.f);
    float q3 = fminf(fmaxf(rintf(__fdiv_rn(v.w, s)), -127.f), 127.f);
    union { __half h[4]; uint2 u; } pk;
    pk.h[0] = __float2half_rn(q0);
    pk.h[1] = __float2half_rn(q1);
    pk.h[2] = __float2half_rn(q2);
    pk.h[3] = __float2half_rn(q3);
    ((uint2*)g_q)[i] = pk.u;
}

// ---------------- kernel 4: build W tile per (j,k) with tensor cores ----------------
// D_p = Ysign_p @ Zsign_p (128x128x16, exact integers via fp32-accum bf16 MMA),
// w = c00*D0 + c01*D1 + sB[m] + sZr[n] + a3s, staged in smem, coalesced fp16 stores.
#define YPITCH 24     // bf16 units per sY row (48 B)
#define ZPITCH 136    // bf16 units per sZ row (272 B)
#define OPITCH 136    // fp16 units per sO row (272 B)
#define SY_OFF  0          // bf16 [2][128*24]  = 12288 B
#define SZ_OFF  12288      // bf16 [2][16*136]  = 8704 B
#define SB_OFF  20992      // float[128]        = 512 B
#define SZR_OFF 21504      // float[128]        = 512 B
#define SO_OFF  22016      // half [128][136]   = 34816 B
#define BW_SMEM 56832

__global__ void __launch_bounds__(256) k_buildw(const float* __restrict__ Ysign,
                                                const float* __restrict__ Zsign,
                                                const float* __restrict__ Yscale,
                                                const float* __restrict__ Zscale,
                                                const float* __restrict__ Aq) {
    extern __shared__ char sm[];
    __nv_bfloat16* sY0 = (__nv_bfloat16*)(sm + SY_OFF);
    __nv_bfloat16* sY1 = (__nv_bfloat16*)(sm + SY_OFF + MM * YPITCH * 2);
    __nv_bfloat16* sZ0 = (__nv_bfloat16*)(sm + SZ_OFF);
    __nv_bfloat16* sZ1 = (__nv_bfloat16*)(sm + SZ_OFF + LL * ZPITCH * 2);
    float* sB  = (float*)(sm + SB_OFF);
    float* sZr = (float*)(sm + SZR_OFF);
    uint32_t* sO = (uint32_t*)(sm + SO_OFF);   // addressed in uint32 units

    const int j = blockIdx.x >> 5;
    const int k = blockIdx.x & 31;
    const int tid = threadIdx.x;
    const int lane = tid & 31;
    const int wid = tid >> 5;

    float ysc[2], zsc[2], a0c[2], a1c[2], a2c[2];
    float a3s = 0.f;
#pragma unroll
    for (int p = 0; p < 2; p++) {
        int idx = (p * JJ + j) * KK + k;
        ysc[p] = Yscale[idx]; zsc[p] = Zscale[idx];
        a0c[p] = Aq[idx * 4 + 0]; a1c[p] = Aq[idx * 4 + 1];
        a2c[p] = Aq[idx * 4 + 2]; a3s += Aq[idx * 4 + 3];
        size_t base = (size_t)idx * (MM * LL);   // 2048 floats (== LL*NN)
        const float4* ys4 = (const float4*)(Ysign + base);
        const float4* zs4 = (const float4*)(Zsign + base);
        __nv_bfloat16* sYp = p ? sY1 : sY0;
        __nv_bfloat16* sZp = p ? sZ1 : sZ0;
#pragma unroll
        for (int i = 0; i < 2; i++) {
            int e4 = tid + i * 256;            // 0..511
            int e = e4 * 4;
            // Y: (m,l) with l fastest, 16 per row
            float4 v = ys4[e4];
            int m = e >> 4, l = e & 15;
            __nv_bfloat162* dy = (__nv_bfloat162*)(&sYp[m * YPITCH + l]);
            dy[0] = __nv_bfloat162{__float2bfloat16(v.x), __float2bfloat16(v.y)};
            dy[1] = __nv_bfloat162{__float2bfloat16(v.z), __float2bfloat16(v.w)};
            // Z: (l,n) with n fastest, 128 per row
            float4 w4 = zs4[e4];
            int zl = e >> 7, n = e & 127;
            __nv_bfloat162* dz = (__nv_bfloat162*)(&sZp[zl * ZPITCH + n]);
            dz[0] = __nv_bfloat162{__float2bfloat16(w4.x), __float2bfloat16(w4.y)};
            dz[1] = __nv_bfloat162{__float2bfloat16(w4.z), __float2bfloat16(w4.w)};
        }
    }
    __syncthreads();

    // row/col sign sums -> coefficient vectors
    if (tid < 128) {
        int m = tid; float s0 = 0.f, s1 = 0.f;
#pragma unroll
        for (int l = 0; l < 16; l++) {
            s0 += __bfloat162float(sY0[m * YPITCH + l]);
            s1 += __bfloat162float(sY1[m * YPITCH + l]);
        }
        sB[m] = a1c[0] * ysc[0] * s0 + a1c[1] * ysc[1] * s1;
    } else {
        int n = tid - 128; float s0 = 0.f, s1 = 0.f;
#pragma unroll
        for (int l = 0; l < 16; l++) {
            s0 += __bfloat162float(sZ0[l * ZPITCH + n]);
            s1 += __bfloat162float(sZ1[l * ZPITCH + n]);
        }
        sZr[n] = a2c[0] * zsc[0] * s0 + a2c[1] * zsc[1] * s1;
    }
    __syncthreads();

    const float c00 = a0c[0] * ysc[0] * zsc[0];
    const float c01 = a0c[1] * ysc[1] * zsc[1];
    const int mb = wid * 16;   // warp's m strip

    // A fragments (16x16, row-major m x l), one per p, loaded once
    uint32_t aoff = (uint32_t)((mb + (lane & 15)) * (YPITCH * 2)) + (uint32_t)((lane >> 4) * 16);
    uint32_t af0[4], af1[4];
    ldsm4(af0, smem_u32(sY0) + aoff);
    ldsm4(af1, smem_u32(sY1) + aoff);

    // B trans-ldsm lane addressing: source rows = l (k dim), cols = n
    uint32_t zoff = (uint32_t)((lane & 15) * (ZPITCH * 2)) + (uint32_t)(((lane >> 4) * 8) * 2);
    const uint32_t zb0 = smem_u32(sZ0) + zoff;
    const uint32_t zb1 = smem_u32(sZ1) + zoff;

    const int r0 = mb + (lane >> 2);
    const int r1 = r0 + 8;
    const float sb0 = sB[r0];
    const float sb1 = sB[r1];
    const int so0 = r0 * (OPITCH / 2);   // uint32 row base
    const int so1 = r1 * (OPITCH / 2);

#pragma unroll
    for (int nc = 0; nc < 4; nc++) {
        const int n0 = nc * 32;
        uint32_t b0a[4], b0b[4], b1a[4], b1b[4];
        ldsm4t(b0a, zb0 + (uint32_t)(n0 * 2));          // p0, n-tiles 0,1
        ldsm4t(b0b, zb0 + (uint32_t)((n0 + 16) * 2));   // p0, n-tiles 2,3
        ldsm4t(b1a, zb1 + (uint32_t)(n0 * 2));
        ldsm4t(b1b, zb1 + (uint32_t)((n0 + 16) * 2));

        float acc0[4][4], acc1[4][4];
#pragma unroll
        for (int t = 0; t < 4; t++)
#pragma unroll
            for (int v = 0; v < 4; v++) { acc0[t][v] = 0.f; acc1[t][v] = 0.f; }

        mma16816_bf(acc0[0], af0, &b0a[0]); mma16816_bf(acc0[1], af0, &b0a[2]);
        mma16816_bf(acc0[2], af0, &b0b[0]); mma16816_bf(acc0[3], af0, &b0b[2]);
        mma16816_bf(acc1[0], af1, &b1a[0]); mma16816_bf(acc1[1], af1, &b1a[2]);
        mma16816_bf(acc1[2], af1, &b1b[0]); mma16816_bf(acc1[3], af1, &b1b[2]);

#pragma unroll
        for (int nt = 0; nt < 4; nt++) {
            const int col = n0 + nt * 8 + (lane & 3) * 2;
            const float2 zr = *(const float2*)(&sZr[col]);
            const float add0 = zr.x + a3s;
            const float add1 = zr.y + a3s;
            float w00 = c00 * acc0[nt][0] + c01 * acc1[nt][0] + sb0 + add0;
            float w01 = c00 * acc0[nt][1] + c01 * acc1[nt][1] + sb0 + add1;
            float w10 = c00 * acc0[nt][2] + c01 * acc1[nt][2] + sb1 + add0;
            float w11 = c00 * acc0[nt][3] + c01 * acc1[nt][3] + sb1 + add1;

            union { __half h[2]; uint32_t u; } pk;
            pk.h[0] = __float2half_rn(w00); pk.h[1] = __float2half_rn(w01);
            sO[so0 + (col >> 1)] = pk.u;
            pk.h[0] = __float2half_rn(w10); pk.h[1] = __float2half_rn(w11);
            sO[so1 + (col >> 1)] = pk.u;
        }
    }
    __syncthreads();

    // coalesced store: 128 rows x 256 B, full 128B lines
    const char* sob = sm + SO_OFF;
    char* gw = (char*)(g_W + (size_t)(j * 128) * KN + k * 128);
#pragma unroll
    for (int it = 0; it < 8; it++) {
        int c = tid + it * 256;         // 0..2047
        int row = c >> 4;
        int seg = c & 15;
        uint4 v = *(const uint4*)(sob + row * (OPITCH * 2) + seg * 16);
        *(uint4*)(gw + (size_t)row * (KN * 2) + seg * 16) = v;
    }
}

// ---------------- kernel 5: warp-MMA GEMM out = act*(q @ W^T) + bias ----------------
// CTA: 512 threads = 16 warps (4 m x 4 n), warp tile 32x32. CTA tile 128(b) x 128(jm).
// K-chunk 64, 4-stage cp.async pipeline, one __syncthreads per chunk.
// Stage: A @+0 (16KB), W @+16KB; 128B rows XOR-swizzled for conflict-free ldmatrix.
__global__ void __launch_bounds__(512, 1) k_gemm(const float* __restrict__ bias,
                                                 float* __restrict__ out) {
    extern __shared__ char smem[];
    const uint32_t sbase = smem_u32(smem);

    const int tid = threadIdx.x;
    const int lane = tid & 31;
    const int wid = tid >> 5;
    const int jt = blockIdx.x;        // jm tile, 0..31
    const int bt = blockIdx.y;        // b tile,  0..3
    const int warp_m = wid & 3;       // 0..3 -> m base warp_m*32
    const int warp_n = wid >> 2;      // 0..3 -> n base warp_n*32

    // ---- cp.async source/dest offsets: 2 x 16B chunks per tile per thread ----
    uint32_t swoff[2];
    const char* srcq[2];
    const char* srcw[2];
    {
        const char* gq = (const char*)(g_q + (size_t)(bt * 128) * KN);
        const char* gw = (const char*)(g_W + (size_t)(jt * 128) * KN);
#pragma unroll
        for (int i = 0; i < 2; i++) {
            int idx = tid + i * 512;            // 0..1023
            int row = idx >> 3;                 // 0..127
            int seg = (idx & 7) * 16;           // byte within 128B row
            swoff[i] = (uint32_t)(row * 128) + ((uint32_t)seg ^ (uint32_t)((row & 7) << 4));
            size_t gb = (size_t)row * (KN * 2) + seg;   // row stride 8192 B
            srcq[i] = gq + gb;
            srcw[i] = gw + gb;
        }
    }

    // ---- prefetch chunks 0..2 ----
#pragma unroll
    for (int s = 0; s < NSTG - 1; s++) {
        uint32_t base = sbase + s * STAGE;
        size_t koff = (size_t)s * 128;          // 64 fp16 = 128 bytes
#pragma unroll
        for (int i = 0; i < 2; i++) {
            cp16(base +         swoff[i], srcq[i] + koff);
            cp16(base + 16384 + swoff[i], srcw[i] + koff);
        }
        CP_COMMIT();
    }

    // ---- ldmatrix lane addressing ----
    const int a_row = warp_m * 32 + (lane & 15);           // + mt*16
    const uint32_t a_hi  = (uint32_t)((lane >> 4) * 16);
    const uint32_t a_swz = (uint32_t)((a_row & 7) << 4);   // invariant under +16
    const int b_g = lane >> 3;                              // 0..3
    const int b_row0 = warp_n * 32 + ((b_g >> 1) << 3) + (lane & 7);  // + i*16
    const uint32_t b_hi  = (uint32_t)((b_g & 1) * 16);
    const uint32_t b_swz = (uint32_t)((b_row0 & 7) << 4);  // invariant under +16

    float acc[2][4][4];
#pragma unroll
    for (int mt = 0; mt < 2; mt++)
#pragma unroll
        for (int nt = 0; nt < 4; nt++)
#pragma unroll
            for (int v = 0; v < 4; v++) acc[mt][nt][v] = 0.f;

    for (int c = 0; c < NCHUNK; c++) {
        CP_WAIT(2);              // chunk c landed (chunks c+1, c+2 may remain)
        __syncthreads();         // all threads see chunk c AND finished compute(c-1)

        // issue chunk c+3 into buffer (c+3)%4 == (c-1)%4, freed by the barrier above
        if (c + 3 < NCHUNK) {
            uint32_t base = sbase + ((c + 3) % NSTG) * STAGE;
            size_t koff = (size_t)(c + 3) * 128;
#pragma unroll
            for (int i = 0; i < 2; i++) {
                cp16(base +         swoff[i], srcq[i] + koff);
                cp16(base + 16384 + swoff[i], srcw[i] + koff);
            }
        }
        CP_COMMIT();             // fixed group accounting (empty at tail)

        const uint32_t bb = sbase + (c % NSTG) * STAGE;
#pragma unroll
        for (int ks = 0; ks < 4; ks++) {
            uint32_t a[2][4];
#pragma unroll
            for (int mt = 0; mt < 2; mt++)
                ldsm4(a[mt], bb + (uint32_t)((a_row + mt * 16) * 128)
                              + (((uint32_t)(ks * 32) + a_hi) ^ a_swz));
            uint32_t bw[4][2];
#pragma unroll
            for (int i = 0; i < 2; i++) {
                uint32_t ro = (uint32_t)((b_row0 + i * 16) * 128)
                            + (((uint32_t)(ks * 32) + b_hi) ^ b_swz);
                uint32_t r[4];
                ldsm4(r, bb + 16384 + ro);
                bw[2*i][0] = r[0]; bw[2*i][1] = r[1]; bw[2*i+1][0] = r[2]; bw[2*i+1][1] = r[3];
            }
#pragma unroll
            for (int mt = 0; mt < 2; mt++)
#pragma unroll
                for (int nt = 0; nt < 4; nt++)
                    mma16816_f16(acc[mt][nt], a[mt], bw[nt]);
        }
    }

    // ---- epilogue: out = acc*act + bias ----
    const float act = g_scale;
    const int orow0 = bt * 128 + warp_m * 32 + (lane >> 2);
    const int ocol0 = jt * 128 + warp_n * 32 + (lane & 3) * 2;
#pragma unroll
    for (int mt = 0; mt < 2; mt++) {
        const int r0 = orow0 + mt * 16;
#pragma unroll
        for (int nt = 0; nt < 4; nt++) {
            const int col = ocol0 + nt * 8;
            const float2 b2 = *(const float2*)(bias + col);
            float2 v0, v1;
            v0.x = acc[mt][nt][0] * act + b2.x;
            v0.y = acc[mt][nt][1] * act + b2.y;
            v1.x = acc[mt][nt][2] * act + b2.x;
            v1.y = acc[mt][nt][3] * act + b2.y;
            *(float2*)(out + (size_t)r0 * JM + col)       = v0;
            *(float2*)(out + (size_t)(r0 + 8) * JM + col) = v1;
        }
    }
}

// ---------------- launcher ----------------
extern "C" void kernel_launch(void* const* d_in, const int* in_sizes, int n_in,
                              void* d_out, int out_size) {
    const float *x = nullptr, *Ys = nullptr, *Zs = nullptr;
    const float *Ysc = nullptr, *Zsc = nullptr, *A = nullptr, *bias = nullptr;
    for (int i = 0; i < n_in; i++) {
        const int s = in_sizes[i];
        const float* p = (const float*)d_in[i];
        if (s == BATCH * KN && !x) x = p;                                        // 2097152
        else if (s == PP * JJ * KK * MM * LL) { if (!Ys) Ys = p; else Zs = p; }  // 4194304 x2
        else if (s == PP * JJ * KK) { if (!Ysc) Ysc = p; else Zsc = p; }         // 2048 x2
        else if (s == PP * JJ * KK * 4) A = p;                                   // 8192
        else if (s == JM) bias = p;                                              // 4096
    }
    float* out = (float*)d_out;

    k_minmax<<<256, 256>>>(x, (BATCH * KN) / 4);
    k_quant<<<(BATCH * KN) / 4 / 256, 256>>>(x);

    cudaFuncSetAttribute(k_buildw, cudaFuncAttributeMaxDynamicSharedMemorySize, BW_SMEM);
    k_buildw<<<JJ * KK, 256, BW_SMEM>>>(Ys, Zs, Ysc, Zsc, A);

    const int smem_bytes = NSTG * STAGE;   // 131072
    cudaFuncSetAttribute(k_gemm, cudaFuncAttributeMaxDynamicSharedMemorySize, smem_bytes);
    dim3 grid(JM / 128, BATCH / 128);
    k_gemm<<<grid, 512, smem_bytes>>>(bias, out);
}

// round 10
// speedup vs baseline: 1.0980x; 1.0980x over previous
#include <cuda_runtime.h>
#include <cuda_bf16.h>
#include <cuda_fp16.h>
#include <cstdint>

// ---------------- problem dims ----------------
#define PP 2
#define JJ 32
#define KK 32
#define MM 128
#define LL 16
#define NN 128
#define BATCH 512
#define KN 4096
#define JM 4096
#define BKC 64                 // GEMM K-chunk (fp16 elements)
#define NCHUNK (KN / BKC)      // 64
#define STAGE 32768            // bytes per pipeline stage (A 16KB + W 16KB)
#define NSTG 4
#define PREP_GRID 128

// ---------------- device scratch (no cudaMalloc allowed) ----------------
__device__ float g_pmax[PREP_GRID];
__device__ float g_pmin[PREP_GRID];
__device__ float g_scale;
__device__ unsigned g_cnt  = 0;
__device__ unsigned g_cnt2 = 0;
__device__ __half g_q[(size_t)BATCH * KN];       // quantized activations (exact ints, fp16)
__device__ __half g_W[(size_t)JM * KN];          // fp16 weight matrix

// ---------------- PTX helpers (sm_100-safe only) ----------------
__device__ __forceinline__ uint32_t smem_u32(const void* p) {
    uint32_t a;
    asm("{ .reg .u64 t; cvta.to.shared.u64 t, %1; cvt.u32.u64 %0, t; }" : "=r"(a) : "l"(p));
    return a;
}

__device__ __forceinline__ void cp16(uint32_t dst, const void* src) {
    asm volatile("cp.async.cg.shared.global [%0], [%1], 16;\n" :: "r"(dst), "l"(src));
}
#define CP_COMMIT() asm volatile("cp.async.commit_group;\n" ::: "memory")
#define CP_WAIT(n)  asm volatile("cp.async.wait_group %0;\n" :: "n"(n) : "memory")

__device__ __forceinline__ void ldsm4(uint32_t* r, uint32_t addr) {
    asm volatile("ldmatrix.sync.aligned.m8n8.x4.shared.b16 {%0,%1,%2,%3}, [%4];"
        : "=r"(r[0]), "=r"(r[1]), "=r"(r[2]), "=r"(r[3]) : "r"(addr));
}
__device__ __forceinline__ void ldsm4t(uint32_t* r, uint32_t addr) {
    asm volatile("ldmatrix.sync.aligned.m8n8.x4.trans.shared.b16 {%0,%1,%2,%3}, [%4];"
        : "=r"(r[0]), "=r"(r[1]), "=r"(r[2]), "=r"(r[3]) : "r"(addr));
}

// bf16 MMA (used in buildw where operands are exact small integers)
__device__ __forceinline__ void mma16816_bf(float* c, const uint32_t* a, const uint32_t* b) {
    asm volatile(
        "mma.sync.aligned.m16n8k16.row.col.f32.bf16.bf16.f32 "
        "{%0,%1,%2,%3}, {%4,%5,%6,%7}, {%8,%9}, {%0,%1,%2,%3};"
        : "+f"(c[0]), "+f"(c[1]), "+f"(c[2]), "+f"(c[3])
        : "r"(a[0]), "r"(a[1]), "r"(a[2]), "r"(a[3]), "r"(b[0]), "r"(b[1]));
}
// fp16 MMA with fp32 accum (main GEMM)
__device__ __forceinline__ void mma16816_f16(float* c, const uint32_t* a, const uint32_t* b) {
    asm volatile(
        "mma.sync.aligned.m16n8k16.row.col.f32.f16.f16.f32 "
        "{%0,%1,%2,%3}, {%4,%5,%6,%7}, {%8,%9}, {%0,%1,%2,%3};"
        : "+f"(c[0]), "+f"(c[1]), "+f"(c[2]), "+f"(c[3])
        : "r"(a[0]), "r"(a[1]), "r"(a[2]), "r"(a[3]), "r"(b[0]), "r"(b[1]));
}

// ---------------- kernel 1: fused minmax + quant (persistent, grid 128) ----------------
// grid 128 <= SM count: all CTAs co-resident, so the counter spin is safe.
// Each CTA owns 4096 float4 (128 CTAs x 4096 x 4 = full 2M-element tensor).
// Counters self-reset (last arriver of phase-2 counter) => deterministic graph replays.
__global__ void __launch_bounds__(256) k_prep(const float* __restrict__ x) {
    const float4* x4 = (const float4*)x;
    const int tid = threadIdx.x;
    const int base = blockIdx.x * 4096 + tid;

    float mx = -3.4e38f, mn = 3.4e38f;
#pragma unroll
    for (int i = 0; i < 16; i++) {
        float4 v = x4[base + i * 256];
        mx = fmaxf(mx, fmaxf(fmaxf(v.x, v.y), fmaxf(v.z, v.w)));
        mn = fminf(mn, fminf(fminf(v.x, v.y), fminf(v.z, v.w)));
    }
    __shared__ float smx[256], smn[256];
    smx[tid] = mx; smn[tid] = mn;
    __syncthreads();
    for (int s = 128; s > 0; s >>= 1) {
        if (tid < s) { smx[tid] = fmaxf(smx[tid], smx[tid + s]); smn[tid] = fminf(smn[tid], smn[tid + s]); }
        __syncthreads();
    }
    if (tid == 0) {
        g_pmax[blockIdx.x] = smx[0];
        g_pmin[blockIdx.x] = smn[0];
        __threadfence();
        atomicAdd(&g_cnt, 1u);
        while (atomicAdd(&g_cnt, 0u) < PREP_GRID) __nanosleep(64);
    }
    __syncthreads();

    // every CTA computes the identical scale from the 128 partials
    if (tid < PREP_GRID) { smx[tid] = g_pmax[tid]; smn[tid] = g_pmin[tid]; }
    __syncthreads();
    for (int s = 64; s > 0; s >>= 1) {
        if (tid < s) { smx[tid] = fmaxf(smx[tid], smx[tid + s]); smn[tid] = fminf(smn[tid], smn[tid + s]); }
        __syncthreads();
    }
    const float scl = fmaxf(__fdiv_rn(smx[0] - smn[0], 254.0f), 1e-8f);   // (max-min)/(2*qmax)
    if (blockIdx.x == 0 && tid == 0) g_scale = scl;

    // phase 2: quantize this CTA's chunk (x is L2-hot from phase 1)
#pragma unroll
    for (int i = 0; i < 16; i++) {
        const int e = base + i * 256;
        float4 v = x4[e];
        float q0 = fminf(fmaxf(rintf(__fdiv_rn(v.x, scl)), -127.f), 127.f);
        float q1 = fminf(fmaxf(rintf(__fdiv_rn(v.y, scl)), -127.f), 127.f);
        float q2 = fminf(fmaxf(rintf(__fdiv_rn(v.z, scl)), -127.f), 127.f);
        float q3 = fminf(fmaxf(rintf(__fdiv_rn(v.w, scl)), -127.f), 127.f);
        union { __half h[4]; uint2 u; } pk;
        pk.h[0] = __float2half_rn(q0);
        pk.h[1] = __float2half_rn(q1);
        pk.h[2] = __float2half_rn(q2);
        pk.h[3] = __float2half_rn(q3);
        ((uint2*)g_q)[e] = pk.u;
    }
    __syncthreads();
    if (tid == 0) {
        unsigned o = atomicAdd(&g_cnt2, 1u);
        if (o == PREP_GRID - 1) { g_cnt = 0; g_cnt2 = 0; }   // reset for next replay
    }
}

// ---------------- kernel 4: build W tile per (j,k) with tensor cores ----------------
// D_p = Ysign_p @ Zsign_p (128x128x16, exact integers via fp32-accum bf16 MMA),
// w = c00*D0 + c01*D1 + sB[m] + sZr[n] + a3s, staged in smem, coalesced fp16 stores.
#define YPITCH 24     // bf16 units per sY row (48 B)
#define ZPITCH 136    // bf16 units per sZ row (272 B)
#define OPITCH 136    // fp16 units per sO row (272 B)
#define SY_OFF  0          // bf16 [2][128*24]  = 12288 B
#define SZ_OFF  12288      // bf16 [2][16*136]  = 8704 B
#define SB_OFF  20992      // float[128]        = 512 B
#define SZR_OFF 21504      // float[128]        = 512 B
#define SO_OFF  22016      // half [128][136]   = 34816 B
#define BW_SMEM 56832

__global__ void __launch_bounds__(256) k_buildw(const float* __restrict__ Ysign,
                                                const float* __restrict__ Zsign,
                                                const float* __restrict__ Yscale,
                                                const float* __restrict__ Zscale,
                                                const float* __restrict__ Aq) {
    extern __shared__ char sm[];
    __nv_bfloat16* sY0 = (__nv_bfloat16*)(sm + SY_OFF);
    __nv_bfloat16* sY1 = (__nv_bfloat16*)(sm + SY_OFF + MM * YPITCH * 2);
    __nv_bfloat16* sZ0 = (__nv_bfloat16*)(sm + SZ_OFF);
    __nv_bfloat16* sZ1 = (__nv_bfloat16*)(sm + SZ_OFF + LL * ZPITCH * 2);
    float* sB  = (float*)(sm + SB_OFF);
    float* sZr = (float*)(sm + SZR_OFF);
    uint32_t* sO = (uint32_t*)(sm + SO_OFF);   // addressed in uint32 units

    const int j = blockIdx.x >> 5;
    const int k = blockIdx.x & 31;
    const int tid = threadIdx.x;
    const int lane = tid & 31;
    const int wid = tid >> 5;

    float ysc[2], zsc[2], a0c[2], a1c[2], a2c[2];
    float a3s = 0.f;
#pragma unroll
    for (int p = 0; p < 2; p++) {
        int idx = (p * JJ + j) * KK + k;
        ysc[p] = Yscale[idx]; zsc[p] = Zscale[idx];
        a0c[p] = Aq[idx * 4 + 0]; a1c[p] = Aq[idx * 4 + 1];
        a2c[p] = Aq[idx * 4 + 2]; a3s += Aq[idx * 4 + 3];
        size_t base = (size_t)idx * (MM * LL);   // 2048 floats (== LL*NN)
        const float4* ys4 = (const float4*)(Ysign + base);
        const float4* zs4 = (const float4*)(Zsign + base);
        __nv_bfloat16* sYp = p ? sY1 : sY0;
        __nv_bfloat16* sZp = p ? sZ1 : sZ0;
#pragma unroll
        for (int i = 0; i < 2; i++) {
            int e4 = tid + i * 256;            // 0..511
            int e = e4 * 4;
            // Y: (m,l) with l fastest, 16 per row
            float4 v = ys4[e4];
            int m = e >> 4, l = e & 15;
            __nv_bfloat162* dy = (__nv_bfloat162*)(&sYp[m * YPITCH + l]);
            dy[0] = __nv_bfloat162{__float2bfloat16(v.x), __float2bfloat16(v.y)};
            dy[1] = __nv_bfloat162{__float2bfloat16(v.z), __float2bfloat16(v.w)};
            // Z: (l,n) with n fastest, 128 per row
            float4 w4 = zs4[e4];
            int zl = e >> 7, n = e & 127;
            __nv_bfloat162* dz = (__nv_bfloat162*)(&sZp[zl * ZPITCH + n]);
            dz[0] = __nv_bfloat162{__float2bfloat16(w4.x), __float2bfloat16(w4.y)};
            dz[1] = __nv_bfloat162{__float2bfloat16(w4.z), __float2bfloat16(w4.w)};
        }
    }
    __syncthreads();

    // row/col sign sums -> coefficient vectors
    if (tid < 128) {
        int m = tid; float s0 = 0.f, s1 = 0.f;
#pragma unroll
        for (int l = 0; l < 16; l++) {
            s0 += __bfloat162float(sY0[m * YPITCH + l]);
            s1 += __bfloat162float(sY1[m * YPITCH + l]);
        }
        sB[m] = a1c[0] * ysc[0] * s0 + a1c[1] * ysc[1] * s1;
    } else {
        int n = tid - 128; float s0 = 0.f, s1 = 0.f;
#pragma unroll
        for (int l = 0; l < 16; l++) {
            s0 += __bfloat162float(sZ0[l * ZPITCH + n]);
            s1 += __bfloat162float(sZ1[l * ZPITCH + n]);
        }
        sZr[n] = a2c[0] * zsc[0] * s0 + a2c[1] * zsc[1] * s1;
    }
    __syncthreads();

    const float c00 = a0c[0] * ysc[0] * zsc[0];
    const float c01 = a0c[1] * ysc[1] * zsc[1];
    const int mb = wid * 16;   // warp's m strip

    // A fragments (16x16, row-major m x l), one per p, loaded once
    uint32_t aoff = (uint32_t)((mb + (lane & 15)) * (YPITCH * 2)) + (uint32_t)((lane >> 4) * 16);
    uint32_t af0[4], af1[4];
    ldsm4(af0, smem_u32(sY0) + aoff);
    ldsm4(af1, smem_u32(sY1) + aoff);

    // B trans-ldsm lane addressing: source rows = l (k dim), cols = n
    uint32_t zoff = (uint32_t)((lane & 15) * (ZPITCH * 2)) + (uint32_t)(((lane >> 4) * 8) * 2);
    const uint32_t zb0 = smem_u32(sZ0) + zoff;
    const uint32_t zb1 = smem_u32(sZ1) + zoff;

    const int r0 = mb + (lane >> 2);
    const int r1 = r0 + 8;
    const float sb0 = sB[r0];
    const float sb1 = sB[r1];
    const int so0 = r0 * (OPITCH / 2);   // uint32 row base
    const int so1 = r1 * (OPITCH / 2);

#pragma unroll
    for (int nc = 0; nc < 4; nc++) {
        const int n0 = nc * 32;
        uint32_t b0a[4], b0b[4], b1a[4], b1b[4];
        ldsm4t(b0a, zb0 + (uint32_t)(n0 * 2));          // p0, n-tiles 0,1
        ldsm4t(b0b, zb0 + (uint32_t)((n0 + 16) * 2));   // p0, n-tiles 2,3
        ldsm4t(b1a, zb1 + (uint32_t)(n0 * 2));
        ldsm4t(b1b, zb1 + (uint32_t)((n0 + 16) * 2));

        float acc0[4][4], acc1[4][4];
#pragma unroll
        for (int t = 0; t < 4; t++)
#pragma unroll
            for (int v = 0; v < 4; v++) { acc0[t][v] = 0.f; acc1[t][v] = 0.f; }

        mma16816_bf(acc0[0], af0, &b0a[0]); mma16816_bf(acc0[1], af0, &b0a[2]);
        mma16816_bf(acc0[2], af0, &b0b[0]); mma16816_bf(acc0[3], af0, &b0b[2]);
        mma16816_bf(acc1[0], af1, &b1a[0]); mma16816_bf(acc1[1], af1, &b1a[2]);
        mma16816_bf(acc1[2], af1, &b1b[0]); mma16816_bf(acc1[3], af1, &b1b[2]);

#pragma unroll
        for (int nt = 0; nt < 4; nt++) {
            const int col = n0 + nt * 8 + (lane & 3) * 2;
            const float2 zr = *(const float2*)(&sZr[col]);
            const float add0 = zr.x + a3s;
            const float add1 = zr.y + a3s;
            float w00 = c00 * acc0[nt][0] + c01 * acc1[nt][0] + sb0 + add0;
            float w01 = c00 * acc0[nt][1] + c01 * acc1[nt][1] + sb0 + add1;
            float w10 = c00 * acc0[nt][2] + c01 * acc1[nt][2] + sb1 + add0;
            float w11 = c00 * acc0[nt][3] + c01 * acc1[nt][3] + sb1 + add1;

            union { __half h[2]; uint32_t u; } pk;
            pk.h[0] = __float2half_rn(w00); pk.h[1] = __float2half_rn(w01);
            sO[so0 + (col >> 1)] = pk.u;
            pk.h[0] = __float2half_rn(w10); pk.h[1] = __float2half_rn(w11);
            sO[so1 + (col >> 1)] = pk.u;
        }
    }
    __syncthreads();

    // coalesced store: 128 rows x 256 B, full 128B lines
    const char* sob = sm + SO_OFF;
    char* gw = (char*)(g_W + (size_t)(j * 128) * KN + k * 128);
#pragma unroll
    for (int it = 0; it < 8; it++) {
        int c = tid + it * 256;         // 0..2047
        int row = c >> 4;
        int seg = c & 15;
        uint4 v = *(const uint4*)(sob + row * (OPITCH * 2) + seg * 16);
        *(uint4*)(gw + (size_t)row * (KN * 2) + seg * 16) = v;
    }
}

// ---------------- kernel 5: warp-MMA GEMM out = act*(q @ W^T) + bias ----------------
// R8 configuration (the measured legacy-HMMA floor): 256 threads = 8 warps (4m x 2n),
// warp tile 32x64, CTA tile 128(b) x 128(jm), K-chunk 64, 4-stage cp.async pipeline,
// one __syncthreads per chunk. Stage: A @+0 (16KB), W @+16KB; XOR-swizzled rows.
__global__ void __launch_bounds__(256, 1) k_gemm(const float* __restrict__ bias,
                                                 float* __restrict__ out) {
    extern __shared__ char smem[];
    const uint32_t sbase = smem_u32(smem);

    const int tid = threadIdx.x;
    const int lane = tid & 31;
    const int wid = tid >> 5;
    const int jt = blockIdx.x;        // jm tile, 0..31
    const int bt = blockIdx.y;        // b tile,  0..3
    const int warp_m = wid >> 1;      // 0..3 -> m base warp_m*32
    const int warp_n = wid & 1;       // 0..1 -> n base warp_n*64

    // ---- cp.async source/dest offsets: 4 x 16B chunks per tile per thread ----
    uint32_t swoff[4];
    const char* srcq[4];
    const char* srcw[4];
    {
        const char* gq = (const char*)(g_q + (size_t)(bt * 128) * KN);
        const char* gw = (const char*)(g_W + (size_t)(jt * 128) * KN);
#pragma unroll
        for (int i = 0; i < 4; i++) {
            int idx = tid + i * 256;            // 0..1023
            int row = idx >> 3;                 // 0..127
            int seg = (idx & 7) * 16;           // byte within 128B row
            swoff[i] = (uint32_t)(row * 128) + ((uint32_t)seg ^ (uint32_t)((row & 7) << 4));
            size_t gb = (size_t)row * (KN * 2) + seg;   // row stride 8192 B
            srcq[i] = gq + gb;
            srcw[i] = gw + gb;
        }
    }

    // ---- prefetch chunks 0..2 ----
#pragma unroll
    for (int s = 0; s < NSTG - 1; s++) {
        uint32_t base = sbase + s * STAGE;
        size_t koff = (size_t)s * 128;          // 64 fp16 = 128 bytes
#pragma unroll
        for (int i = 0; i < 4; i++) {
            cp16(base +         swoff[i], srcq[i] + koff);
            cp16(base + 16384 + swoff[i], srcw[i] + koff);
        }
        CP_COMMIT();
    }

    // ---- ldmatrix lane addressing ----
    const int a_row = warp_m * 32 + (lane & 15);           // + mt*16
    const uint32_t a_hi  = (uint32_t)((lane >> 4) * 16);
    const uint32_t a_swz = (uint32_t)((a_row & 7) << 4);   // invariant under +16
    const int b_g = lane >> 3;                              // 0..3
    const int b_row0 = warp_n * 64 + ((b_g >> 1) << 3) + (lane & 7);  // + i*16
    const uint32_t b_hi  = (uint32_t)((b_g & 1) * 16);
    const uint32_t b_swz = (uint32_t)((b_row0 & 7) << 4);  // invariant under +16

    float acc[2][8][4];
#pragma unroll
    for (int mt = 0; mt < 2; mt++)
#pragma unroll
        for (int nt = 0; nt < 8; nt++)
#pragma unroll
            for (int v = 0; v < 4; v++) acc[mt][nt][v] = 0.f;

    for (int c = 0; c < NCHUNK; c++) {
        CP_WAIT(2);              // chunk c landed (chunks c+1, c+2 may remain)
        __syncthreads();         // all threads see chunk c AND finished compute(c-1)

        // issue chunk c+3 into buffer (c+3)%4 == (c-1)%4, freed by the barrier above
        if (c + 3 < NCHUNK) {
            uint32_t base = sbase + ((c + 3) % NSTG) * STAGE;
            size_t koff = (size_t)(c + 3) * 128;
#pragma unroll
            for (int i = 0; i < 4; i++) {
                cp16(base +         swoff[i], srcq[i] + koff);
                cp16(base + 16384 + swoff[i], srcw[i] + koff);
            }
        }
        CP_COMMIT();             // fixed group accounting (empty at tail)

        const uint32_t bb = sbase + (c % NSTG) * STAGE;
#pragma unroll
        for (int ks = 0; ks < 4; ks++) {
            uint32_t a[2][4];
#pragma unroll
            for (int mt = 0; mt < 2; mt++)
                ldsm4(a[mt], bb + (uint32_t)((a_row + mt * 16) * 128)
                              + (((uint32_t)(ks * 32) + a_hi) ^ a_swz));
            uint32_t bw[8][2];
#pragma unroll
            for (int i = 0; i < 4; i++) {
                uint32_t ro = (uint32_t)((b_row0 + i * 16) * 128)
                            + (((uint32_t)(ks * 32) + b_hi) ^ b_swz);
                uint32_t r[4];
                ldsm4(r, bb + 16384 + ro);
                bw[2*i][0] = r[0]; bw[2*i][1] = r[1]; bw[2*i+1][0] = r[2]; bw[2*i+1][1] = r[3];
            }
#pragma unroll
            for (int mt = 0; mt < 2; mt++)
#pragma unroll
                for (int nt = 0; nt < 8; nt++)
                    mma16816_f16(acc[mt][nt], a[mt], bw[nt]);
        }
    }

    // ---- epilogue: out = acc*act + bias ----
    const float act = g_scale;
    const int orow0 = bt * 128 + warp_m * 32 + (lane >> 2);
    const int ocol0 = jt * 128 + warp_n * 64 + (lane & 3) * 2;
#pragma unroll
    for (int mt = 0; mt < 2; mt++) {
        const int r0 = orow0 + mt * 16;
#pragma unroll
        for (int nt = 0; nt < 8; nt++) {
            const int col = ocol0 + nt * 8;
            const float2 b2 = *(const float2*)(bias + col);
            float2 v0, v1;
            v0.x = acc[mt][nt][0] * act + b2.x;
            v0.y = acc[mt][nt][1] * act + b2.y;
            v1.x = acc[mt][nt][2] * act + b2.x;
            v1.y = acc[mt][nt][3] * act + b2.y;
            *(float2*)(out + (size_t)r0 * JM + col)       = v0;
            *(float2*)(out + (size_t)(r0 + 8) * JM + col) = v1;
        }
    }
}

// ---------------- launcher ----------------
extern "C" void kernel_launch(void* const* d_in, const int* in_sizes, int n_in,
                              void* d_out, int out_size) {
    const float *x = nullptr, *Ys = nullptr, *Zs = nullptr;
    const float *Ysc = nullptr, *Zsc = nullptr, *A = nullptr, *bias = nullptr;
    for (int i = 0; i < n_in; i++) {
        const int s = in_sizes[i];
        const float* p = (const float*)d_in[i];
        if (s == BATCH * KN && !x) x = p;                                        // 2097152
        else if (s == PP * JJ * KK * MM * LL) { if (!Ys) Ys = p; else Zs = p; }  // 4194304 x2
        else if (s == PP * JJ * KK) { if (!Ysc) Ysc = p; else Zsc = p; }         // 2048 x2
        else if (s == PP * JJ * KK * 4) A = p;                                   // 8192
        else if (s == JM) bias = p;                                              // 4096
    }
    float* out = (float*)d_out;

    k_prep<<<PREP_GRID, 256>>>(x);

    cudaFuncSetAttribute(k_buildw, cudaFuncAttributeMaxDynamicSharedMemorySize, BW_SMEM);
    k_buildw<<<JJ * KK, 256, BW_SMEM>>>(Ys, Zs, Ysc, Zsc, A);

    const int smem_bytes = NSTG * STAGE;   // 131072
    cudaFuncSetAttribute(k_gemm, cudaFuncAttributeMaxDynamicSharedMemorySize, smem_bytes);
    dim3 grid(JM / 128, BATCH / 128);
    k_gemm<<<grid, 256, smem_bytes>>>(bias, out);
}

// round 11
// speedup vs baseline: 1.1842x; 1.0785x over previous
#include <cuda_runtime.h>
#include <cuda_bf16.h>
#include <cuda_fp16.h>
#include <cstdint>

// ---------------- problem dims ----------------
#define PP 2
#define JJ 32
#define KK 32
#define MM 128
#define LL 16
#define NN 128
#define BATCH 512
#define KN 4096
#define JM 4096
#define BKC 64                 // GEMM K-chunk (fp16 elements)
#define NCHUNK (KN / BKC)      // 64
#define STAGE 32768            // bytes per pipeline stage (A 16KB + W 16KB)
#define NSTG 4
#define PREP_GRID 128

// ---------------- device scratch (no cudaMalloc allowed) ----------------
__device__ float g_pmax[PREP_GRID];
__device__ float g_pmin[PREP_GRID];
__device__ float g_scale;
__device__ unsigned g_cnt  = 0;
__device__ unsigned g_cnt2 = 0;
__device__ __half g_q[(size_t)BATCH * KN];       // quantized activations (exact ints, fp16)
__device__ __half g_W[(size_t)JM * KN];          // fp16 weight matrix

// ---------------- PTX helpers (sm_100-safe only) ----------------
__device__ __forceinline__ uint32_t smem_u32(const void* p) {
    uint32_t a;
    asm("{ .reg .u64 t; cvta.to.shared.u64 t, %1; cvt.u32.u64 %0, t; }" : "=r"(a) : "l"(p));
    return a;
}

__device__ __forceinline__ void cp16(uint32_t dst, const void* src) {
    asm volatile("cp.async.cg.shared.global [%0], [%1], 16;\n" :: "r"(dst), "l"(src));
}
#define CP_COMMIT() asm volatile("cp.async.commit_group;\n" ::: "memory")
#define CP_WAIT(n)  asm volatile("cp.async.wait_group %0;\n" :: "n"(n) : "memory")

__device__ __forceinline__ void ldsm4(uint32_t* r, uint32_t addr) {
    asm volatile("ldmatrix.sync.aligned.m8n8.x4.shared.b16 {%0,%1,%2,%3}, [%4];"
        : "=r"(r[0]), "=r"(r[1]), "=r"(r[2]), "=r"(r[3]) : "r"(addr));
}
__device__ __forceinline__ void ldsm4t(uint32_t* r, uint32_t addr) {
    asm volatile("ldmatrix.sync.aligned.m8n8.x4.trans.shared.b16 {%0,%1,%2,%3}, [%4];"
        : "=r"(r[0]), "=r"(r[1]), "=r"(r[2]), "=r"(r[3]) : "r"(addr));
}

// bf16 MMA (used in buildw where operands are exact small integers)
__device__ __forceinline__ void mma16816_bf(float* c, const uint32_t* a, const uint32_t* b) {
    asm volatile(
        "mma.sync.aligned.m16n8k16.row.col.f32.bf16.bf16.f32 "
        "{%0,%1,%2,%3}, {%4,%5,%6,%7}, {%8,%9}, {%0,%1,%2,%3};"
        : "+f"(c[0]), "+f"(c[1]), "+f"(c[2]), "+f"(c[3])
        : "r"(a[0]), "r"(a[1]), "r"(a[2]), "r"(a[3]), "r"(b[0]), "r"(b[1]));
}
// fp16 MMA with fp32 accum (main GEMM)
__device__ __forceinline__ void mma16816_f16(float* c, const uint32_t* a, const uint32_t* b) {
    asm volatile(
        "mma.sync.aligned.m16n8k16.row.col.f32.f16.f16.f32 "
        "{%0,%1,%2,%3}, {%4,%5,%6,%7}, {%8,%9}, {%0,%1,%2,%3};"
        : "+f"(c[0]), "+f"(c[1]), "+f"(c[2]), "+f"(c[3])
        : "r"(a[0]), "r"(a[1]), "r"(a[2]), "r"(a[3]), "r"(b[0]), "r"(b[1]));
}

// ---------------- smem layout for the fused prep+buildw kernel ----------------
#define YPITCH 24     // bf16 units per sY row (48 B)
#define ZPITCH 136    // bf16 units per sZ row (272 B)
#define OPITCH 136    // fp16 units per sO row (272 B)
#define SY_OFF  0          // bf16 [2][128*24]  = 12288 B
#define SZ_OFF  12288      // bf16 [2][16*136]  = 8704 B
#define SB_OFF  20992      // float[128]        = 512 B
#define SZR_OFF 21504      // float[128]        = 512 B
#define SO_OFF  22016      // half [128][136]   = 34816 B
#define BW_SMEM 56832

// ---------------- prep path: fused minmax + quant (CTAs 0..127, all wave-1 resident) ----------------
__device__ __forceinline__ void prep_body(const float* __restrict__ x, char* sm) {
    float* smx = (float*)sm;           // 1024 B
    float* smn = (float*)(sm + 1024);  // 1024 B
    const float4* x4 = (const float4*)x;
    const int tid = threadIdx.x;
    const int base = blockIdx.x * 4096 + tid;

    float mx = -3.4e38f, mn = 3.4e38f;
#pragma unroll
    for (int i = 0; i < 16; i++) {
        float4 v = x4[base + i * 256];
        mx = fmaxf(mx, fmaxf(fmaxf(v.x, v.y), fmaxf(v.z, v.w)));
        mn = fminf(mn, fminf(fminf(v.x, v.y), fminf(v.z, v.w)));
    }
    smx[tid] = mx; smn[tid] = mn;
    __syncthreads();
    for (int s = 128; s > 0; s >>= 1) {
        if (tid < s) { smx[tid] = fmaxf(smx[tid], smx[tid + s]); smn[tid] = fminf(smn[tid], smn[tid + s]); }
        __syncthreads();
    }
    if (tid == 0) {
        g_pmax[blockIdx.x] = smx[0];
        g_pmin[blockIdx.x] = smn[0];
        __threadfence();
        atomicAdd(&g_cnt, 1u);
        while (atomicAdd(&g_cnt, 0u) < PREP_GRID) __nanosleep(64);
    }
    __syncthreads();

    // every prep CTA computes the identical scale from the 128 partials
    if (tid < PREP_GRID) { smx[tid] = g_pmax[tid]; smn[tid] = g_pmin[tid]; }
    __syncthreads();
    for (int s = 64; s > 0; s >>= 1) {
        if (tid < s) { smx[tid] = fmaxf(smx[tid], smx[tid + s]); smn[tid] = fminf(smn[tid], smn[tid + s]); }
        __syncthreads();
    }
    const float scl = fmaxf(__fdiv_rn(smx[0] - smn[0], 254.0f), 1e-8f);   // (max-min)/(2*qmax)
    if (blockIdx.x == 0 && tid == 0) g_scale = scl;

    // phase 2: quantize this CTA's chunk (x is L2-hot from phase 1)
#pragma unroll
    for (int i = 0; i < 16; i++) {
        const int e = base + i * 256;
        float4 v = x4[e];
        float q0 = fminf(fmaxf(rintf(__fdiv_rn(v.x, scl)), -127.f), 127.f);
        float q1 = fminf(fmaxf(rintf(__fdiv_rn(v.y, scl)), -127.f), 127.f);
        float q2 = fminf(fmaxf(rintf(__fdiv_rn(v.z, scl)), -127.f), 127.f);
        float q3 = fminf(fmaxf(rintf(__fdiv_rn(v.w, scl)), -127.f), 127.f);
        union { __half h[4]; uint2 u; } pk;
        pk.h[0] = __float2half_rn(q0);
        pk.h[1] = __float2half_rn(q1);
        pk.h[2] = __float2half_rn(q2);
        pk.h[3] = __float2half_rn(q3);
        ((uint2*)g_q)[e] = pk.u;
    }
    __syncthreads();
    if (tid == 0) {
        unsigned o = atomicAdd(&g_cnt2, 1u);
        if (o == PREP_GRID - 1) { g_cnt = 0; g_cnt2 = 0; }   // reset for next replay
    }
}

// ---------------- buildw path: W tile per (j,k) with tensor cores ----------------
__device__ __forceinline__ void buildw_body(int bid, char* sm,
                                            const float* __restrict__ Ysign,
                                            const float* __restrict__ Zsign,
                                            const float* __restrict__ Yscale,
                                            const float* __restrict__ Zscale,
                                            const float* __restrict__ Aq) {
    __nv_bfloat16* sY0 = (__nv_bfloat16*)(sm + SY_OFF);
    __nv_bfloat16* sY1 = (__nv_bfloat16*)(sm + SY_OFF + MM * YPITCH * 2);
    __nv_bfloat16* sZ0 = (__nv_bfloat16*)(sm + SZ_OFF);
    __nv_bfloat16* sZ1 = (__nv_bfloat16*)(sm + SZ_OFF + LL * ZPITCH * 2);
    float* sB  = (float*)(sm + SB_OFF);
    float* sZr = (float*)(sm + SZR_OFF);
    uint32_t* sO = (uint32_t*)(sm + SO_OFF);   // addressed in uint32 units

    const int j = bid >> 5;
    const int k = bid & 31;
    const int tid = threadIdx.x;
    const int lane = tid & 31;
    const int wid = tid >> 5;

    float ysc[2], zsc[2], a0c[2], a1c[2], a2c[2];
    float a3s = 0.f;
#pragma unroll
    for (int p = 0; p < 2; p++) {
        int idx = (p * JJ + j) * KK + k;
        ysc[p] = Yscale[idx]; zsc[p] = Zscale[idx];
        a0c[p] = Aq[idx * 4 + 0]; a1c[p] = Aq[idx * 4 + 1];
        a2c[p] = Aq[idx * 4 + 2]; a3s += Aq[idx * 4 + 3];
        size_t base = (size_t)idx * (MM * LL);   // 2048 floats (== LL*NN)
        const float4* ys4 = (const float4*)(Ysign + base);
        const float4* zs4 = (const float4*)(Zsign + base);
        __nv_bfloat16* sYp = p ? sY1 : sY0;
        __nv_bfloat16* sZp = p ? sZ1 : sZ0;
#pragma unroll
        for (int i = 0; i < 2; i++) {
            int e4 = tid + i * 256;            // 0..511
            int e = e4 * 4;
            // Y: (m,l) with l fastest, 16 per row
            float4 v = ys4[e4];
            int m = e >> 4, l = e & 15;
            __nv_bfloat162* dy = (__nv_bfloat162*)(&sYp[m * YPITCH + l]);
            dy[0] = __nv_bfloat162{__float2bfloat16(v.x), __float2bfloat16(v.y)};
            dy[1] = __nv_bfloat162{__float2bfloat16(v.z), __float2bfloat16(v.w)};
            // Z: (l,n) with n fastest, 128 per row
            float4 w4 = zs4[e4];
            int zl = e >> 7, n = e & 127;
            __nv_bfloat162* dz = (__nv_bfloat162*)(&sZp[zl * ZPITCH + n]);
            dz[0] = __nv_bfloat162{__float2bfloat16(w4.x), __float2bfloat16(w4.y)};
            dz[1] = __nv_bfloat162{__float2bfloat16(w4.z), __float2bfloat16(w4.w)};
        }
    }
    __syncthreads();

    // row/col sign sums -> coefficient vectors
    if (tid < 128) {
        int m = tid; float s0 = 0.f, s1 = 0.f;
#pragma unroll
        for (int l = 0; l < 16; l++) {
            s0 += __bfloat162float(sY0[m * YPITCH + l]);
            s1 += __bfloat162float(sY1[m * YPITCH + l]);
        }
        sB[m] = a1c[0] * ysc[0] * s0 + a1c[1] * ysc[1] * s1;
    } else {
        int n = tid - 128; float s0 = 0.f, s1 = 0.f;
#pragma unroll
        for (int l = 0; l < 16; l++) {
            s0 += __bfloat162float(sZ0[l * ZPITCH + n]);
            s1 += __bfloat162float(sZ1[l * ZPITCH + n]);
        }
        sZr[n] = a2c[0] * zsc[0] * s0 + a2c[1] * zsc[1] * s1;
    }
    __syncthreads();

    const float c00 = a0c[0] * ysc[0] * zsc[0];
    const float c01 = a0c[1] * ysc[1] * zsc[1];
    const int mb = wid * 16;   // warp's m strip

    // A fragments (16x16, row-major m x l), one per p, loaded once
    uint32_t aoff = (uint32_t)((mb + (lane & 15)) * (YPITCH * 2)) + (uint32_t)((lane >> 4) * 16);
    uint32_t af0[4], af1[4];
    ldsm4(af0, smem_u32(sY0) + aoff);
    ldsm4(af1, smem_u32(sY1) + aoff);

    // B trans-ldsm lane addressing: source rows = l (k dim), cols = n
    uint32_t zoff = (uint32_t)((lane & 15) * (ZPITCH * 2)) + (uint32_t)(((lane >> 4) * 8) * 2);
    const uint32_t zb0 = smem_u32(sZ0) + zoff;
    const uint32_t zb1 = smem_u32(sZ1) + zoff;

    const int r0 = mb + (lane >> 2);
    const int r1 = r0 + 8;
    const float sb0 = sB[r0];
    const float sb1 = sB[r1];
    const int so0 = r0 * (OPITCH / 2);   // uint32 row base
    const int so1 = r1 * (OPITCH / 2);

#pragma unroll
    for (int nc = 0; nc < 4; nc++) {
        const int n0 = nc * 32;
        uint32_t b0a[4], b0b[4], b1a[4], b1b[4];
        ldsm4t(b0a, zb0 + (uint32_t)(n0 * 2));          // p0, n-tiles 0,1
        ldsm4t(b0b, zb0 + (uint32_t)((n0 + 16) * 2));   // p0, n-tiles 2,3
        ldsm4t(b1a, zb1 + (uint32_t)(n0 * 2));
        ldsm4t(b1b, zb1 + (uint32_t)((n0 + 16) * 2));

        float acc0[4][4], acc1[4][4];
#pragma unroll
        for (int t = 0; t < 4; t++)
#pragma unroll
            for (int v = 0; v < 4; v++) { acc0[t][v] = 0.f; acc1[t][v] = 0.f; }

        mma16816_bf(acc0[0], af0, &b0a[0]); mma16816_bf(acc0[1], af0, &b0a[2]);
        mma16816_bf(acc0[2], af0, &b0b[0]); mma16816_bf(acc0[3], af0, &b0b[2]);
        mma16816_bf(acc1[0], af1, &b1a[0]); mma16816_bf(acc1[1], af1, &b1a[2]);
        mma16816_bf(acc1[2], af1, &b1b[0]); mma16816_bf(acc1[3], af1, &b1b[2]);

#pragma unroll
        for (int nt = 0; nt < 4; nt++) {
            const int col = n0 + nt * 8 + (lane & 3) * 2;
            const float2 zr = *(const float2*)(&sZr[col]);
            const float add0 = zr.x + a3s;
            const float add1 = zr.y + a3s;
            float w00 = c00 * acc0[nt][0] + c01 * acc1[nt][0] + sb0 + add0;
            float w01 = c00 * acc0[nt][1] + c01 * acc1[nt][1] + sb0 + add1;
            float w10 = c00 * acc0[nt][2] + c01 * acc1[nt][2] + sb1 + add0;
            float w11 = c00 * acc0[nt][3] + c01 * acc1[nt][3] + sb1 + add1;

            union { __half h[2]; uint32_t u; } pk;
            pk.h[0] = __float2half_rn(w00); pk.h[1] = __float2half_rn(w01);
            sO[so0 + (col >> 1)] = pk.u;
            pk.h[0] = __float2half_rn(w10); pk.h[1] = __float2half_rn(w11);
            sO[so1 + (col >> 1)] = pk.u;
        }
    }
    __syncthreads();

    // coalesced store: 128 rows x 256 B, full 128B lines
    const char* sob = sm + SO_OFF;
    char* gw = (char*)(g_W + (size_t)(j * 128) * KN + k * 128);
#pragma unroll
    for (int it = 0; it < 8; it++) {
        int c = tid + it * 256;         // 0..2047
        int row = c >> 4;
        int seg = c & 15;
        uint4 v = *(const uint4*)(sob + row * (OPITCH * 2) + seg * 16);
        *(uint4*)(gw + (size_t)row * (KN * 2) + seg * 16) = v;
    }
}

// ---------------- fused kernel: prep (CTAs 0..127) + buildw (CTAs 128..1151) ----------------
// Independent work; fusing overlaps prep's DRAM-latency stalls with buildw's tensor work.
// Prep CTAs are first => all 128 are wave-1 co-resident (capacity >= 3/SM * 148 = 444),
// so the grid-wide spin barrier inside prep cannot deadlock.
__global__ void __launch_bounds__(256) k_pb(const float* __restrict__ x,
                                            const float* __restrict__ Ysign,
                                            const float* __restrict__ Zsign,
                                            const float* __restrict__ Yscale,
                                            const float* __restrict__ Zscale,
                                            const float* __restrict__ Aq) {
    extern __shared__ char sm[];
    if (blockIdx.x < PREP_GRID) {
        prep_body(x, sm);
    } else {
        buildw_body(blockIdx.x - PREP_GRID, sm, Ysign, Zsign, Yscale, Zscale, Aq);
    }
}

// ---------------- kernel: warp-MMA GEMM out = act*(q @ W^T) + bias ----------------
// R8 configuration (the measured legacy-HMMA floor): 256 threads = 8 warps (4m x 2n),
// warp tile 32x64, CTA tile 128(b) x 128(jm), K-chunk 64, 4-stage cp.async pipeline,
// one __syncthreads per chunk. Stage: A @+0 (16KB), W @+16KB; XOR-swizzled rows.
__global__ void __launch_bounds__(256, 1) k_gemm(const float* __restrict__ bias,
                                                 float* __restrict__ out) {
    extern __shared__ char smem[];
    const uint32_t sbase = smem_u32(smem);

    const int tid = threadIdx.x;
    const int lane = tid & 31;
    const int wid = tid >> 5;
    const int jt = blockIdx.x;        // jm tile, 0..31
    const int bt = blockIdx.y;        // b tile,  0..3
    const int warp_m = wid >> 1;      // 0..3 -> m base warp_m*32
    const int warp_n = wid & 1;       // 0..1 -> n base warp_n*64

    // ---- cp.async source/dest offsets: 4 x 16B chunks per tile per thread ----
    uint32_t swoff[4];
    const char* srcq[4];
    const char* srcw[4];
    {
        const char* gq = (const char*)(g_q + (size_t)(bt * 128) * KN);
        const char* gw = (const char*)(g_W + (size_t)(jt * 128) * KN);
#pragma unroll
        for (int i = 0; i < 4; i++) {
            int idx = tid + i * 256;            // 0..1023
            int row = idx >> 3;                 // 0..127
            int seg = (idx & 7) * 16;           // byte within 128B row
            swoff[i] = (uint32_t)(row * 128) + ((uint32_t)seg ^ (uint32_t)((row & 7) << 4));
            size_t gb = (size_t)row * (KN * 2) + seg;   // row stride 8192 B
            srcq[i] = gq + gb;
            srcw[i] = gw + gb;
        }
    }

    // ---- prefetch chunks 0..2 ----
#pragma unroll
    for (int s = 0; s < NSTG - 1; s++) {
        uint32_t base = sbase + s * STAGE;
        size_t koff = (size_t)s * 128;          // 64 fp16 = 128 bytes
#pragma unroll
        for (int i = 0; i < 4; i++) {
            cp16(base +         swoff[i], srcq[i] + koff);
            cp16(base + 16384 + swoff[i], srcw[i] + koff);
        }
        CP_COMMIT();
    }

    // ---- ldmatrix lane addressing ----
    const int a_row = warp_m * 32 + (lane & 15);           // + mt*16
    const uint32_t a_hi  = (uint32_t)((lane >> 4) * 16);
    const uint32_t a_swz = (uint32_t)((a_row & 7) << 4);   // invariant under +16
    const int b_g = lane >> 3;                              // 0..3
    const int b_row0 = warp_n * 64 + ((b_g >> 1) << 3) + (lane & 7);  // + i*16
    const uint32_t b_hi  = (uint32_t)((b_g & 1) * 16);
    const uint32_t b_swz = (uint32_t)((b_row0 & 7) << 4);  // invariant under +16

    float acc[2][8][4];
#pragma unroll
    for (int mt = 0; mt < 2; mt++)
#pragma unroll
        for (int nt = 0; nt < 8; nt++)
#pragma unroll
            for (int v = 0; v < 4; v++) acc[mt][nt][v] = 0.f;

    for (int c = 0; c < NCHUNK; c++) {
        CP_WAIT(2);              // chunk c landed (chunks c+1, c+2 may remain)
        __syncthreads();         // all threads see chunk c AND finished compute(c-1)

        // issue chunk c+3 into buffer (c+3)%4 == (c-1)%4, freed by the barrier above
        if (c + 3 < NCHUNK) {
            uint32_t base = sbase + ((c + 3) % NSTG) * STAGE;
            size_t koff = (size_t)(c + 3) * 128;
#pragma unroll
            for (int i = 0; i < 4; i++) {
                cp16(base +         swoff[i], srcq[i] + koff);
                cp16(base + 16384 + swoff[i], srcw[i] + koff);
            }
        }
        CP_COMMIT();             // fixed group accounting (empty at tail)

        const uint32_t bb = sbase + (c % NSTG) * STAGE;
#pragma unroll
        for (int ks = 0; ks < 4; ks++) {
            uint32_t a[2][4];
#pragma unroll
            for (int mt = 0; mt < 2; mt++)
                ldsm4(a[mt], bb + (uint32_t)((a_row + mt * 16) * 128)
                              + (((uint32_t)(ks * 32) + a_hi) ^ a_swz));
            uint32_t bw[8][2];
#pragma unroll
            for (int i = 0; i < 4; i++) {
                uint32_t ro = (uint32_t)((b_row0 + i * 16) * 128)
                            + (((uint32_t)(ks * 32) + b_hi) ^ b_swz);
                uint32_t r[4];
                ldsm4(r, bb + 16384 + ro);
                bw[2*i][0] = r[0]; bw[2*i][1] = r[1]; bw[2*i+1][0] = r[2]; bw[2*i+1][1] = r[3];
            }
#pragma unroll
            for (int mt = 0; mt < 2; mt++)
#pragma unroll
                for (int nt = 0; nt < 8; nt++)
                    mma16816_f16(acc[mt][nt], a[mt], bw[nt]);
        }
    }

    // ---- epilogue: out = acc*act + bias ----
    const float act = g_scale;
    const int orow0 = bt * 128 + warp_m * 32 + (lane >> 2);
    const int ocol0 = jt * 128 + warp_n * 64 + (lane & 3) * 2;
#pragma unroll
    for (int mt = 0; mt < 2; mt++) {
        const int r0 = orow0 + mt * 16;
#pragma unroll
        for (int nt = 0; nt < 8; nt++) {
            const int col = ocol0 + nt * 8;
            const float2 b2 = *(const float2*)(bias + col);
            float2 v0, v1;
            v0.x = acc[mt][nt][0] * act + b2.x;
            v0.y = acc[mt][nt][1] * act + b2.y;
            v1.x = acc[mt][nt][2] * act + b2.x;
            v1.y = acc[mt][nt][3] * act + b2.y;
            *(float2*)(out + (size_t)r0 * JM + col)       = v0;
            *(float2*)(out + (size_t)(r0 + 8) * JM + col) = v1;
        }
    }
}

// ---------------- launcher ----------------
extern "C" void kernel_launch(void* const* d_in, const int* in_sizes, int n_in,
                              void* d_out, int out_size) {
    const float *x = nullptr, *Ys = nullptr, *Zs = nullptr;
    const float *Ysc = nullptr, *Zsc = nullptr, *A = nullptr, *bias = nullptr;
    for (int i = 0; i < n_in; i++) {
        const int s = in_sizes[i];
        const float* p = (const float*)d_in[i];
        if (s == BATCH * KN && !x) x = p;                                        // 2097152
        else if (s == PP * JJ * KK * MM * LL) { if (!Ys) Ys = p; else Zs = p; }  // 4194304 x2
        else if (s == PP * JJ * KK) { if (!Ysc) Ysc = p; else Zsc = p; }         // 2048 x2
        else if (s == PP * JJ * KK * 4) A = p;                                   // 8192
        else if (s == JM) bias = p;                                              // 4096
    }
    float* out = (float*)d_out;

    cudaFuncSetAttribute(k_pb, cudaFuncAttributeMaxDynamicSharedMemorySize, BW_SMEM);
    k_pb<<<PREP_GRID + JJ * KK, 256, BW_SMEM>>>(x, Ys, Zs, Ysc, Zsc, A);

    const int smem_bytes = NSTG * STAGE;   // 131072
    cudaFuncSetAttribute(k_gemm, cudaFuncAttributeMaxDynamicSharedMemorySize, smem_bytes);
    dim3 grid(JM / 128, BATCH / 128);
    k_gemm<<<grid, 256, smem_bytes>>>(bias, out);
}

// round 12
// speedup vs baseline: 1.2851x; 1.0852x over previous
#include <cuda_runtime.h>
#include <cuda_bf16.h>
#include <cuda_fp16.h>
#include <cstdint>

// ---------------- problem dims ----------------
#define PP 2
#define JJ 32
#define KK 32
#define MM 128
#define LL 16
#define NN 128
#define BATCH 512
#define KN 4096
#define JM 4096
#define BKC 64                 // GEMM K-chunk (fp16 elements)
#define NCHUNK (KN / BKC)      // 64
#define STAGE 24576            // bytes per pipeline stage (A 8KB + W 16KB)
#define NSTG 4
#define PREP_GRID 128

// ---------------- device scratch (no cudaMalloc allowed) ----------------
__device__ float g_pmax[PREP_GRID];
__device__ float g_pmin[PREP_GRID];
__device__ float g_scale;
__device__ unsigned g_cnt  = 0;
__device__ unsigned g_cnt2 = 0;
__device__ __half g_q[(size_t)BATCH * KN];       // quantized activations (exact ints, fp16)
__device__ __half g_W[(size_t)JM * KN];          // fp16 weight matrix

// ---------------- PTX helpers (sm_100-safe only) ----------------
__device__ __forceinline__ uint32_t smem_u32(const void* p) {
    uint32_t a;
    asm("{ .reg .u64 t; cvta.to.shared.u64 t, %1; cvt.u32.u64 %0, t; }" : "=r"(a) : "l"(p));
    return a;
}

__device__ __forceinline__ void cp16(uint32_t dst, const void* src) {
    asm volatile("cp.async.cg.shared.global [%0], [%1], 16;\n" :: "r"(dst), "l"(src));
}
#define CP_COMMIT() asm volatile("cp.async.commit_group;\n" ::: "memory")
#define CP_WAIT(n)  asm volatile("cp.async.wait_group %0;\n" :: "n"(n) : "memory")

__device__ __forceinline__ void ldsm4(uint32_t* r, uint32_t addr) {
    asm volatile("ldmatrix.sync.aligned.m8n8.x4.shared.b16 {%0,%1,%2,%3}, [%4];"
        : "=r"(r[0]), "=r"(r[1]), "=r"(r[2]), "=r"(r[3]) : "r"(addr));
}
__device__ __forceinline__ void ldsm4t(uint32_t* r, uint32_t addr) {
    asm volatile("ldmatrix.sync.aligned.m8n8.x4.trans.shared.b16 {%0,%1,%2,%3}, [%4];"
        : "=r"(r[0]), "=r"(r[1]), "=r"(r[2]), "=r"(r[3]) : "r"(addr));
}

// bf16 MMA (used in buildw where operands are exact small integers)
__device__ __forceinline__ void mma16816_bf(float* c, const uint32_t* a, const uint32_t* b) {
    asm volatile(
        "mma.sync.aligned.m16n8k16.row.col.f32.bf16.bf16.f32 "
        "{%0,%1,%2,%3}, {%4,%5,%6,%7}, {%8,%9}, {%0,%1,%2,%3};"
        : "+f"(c[0]), "+f"(c[1]), "+f"(c[2]), "+f"(c[3])
        : "r"(a[0]), "r"(a[1]), "r"(a[2]), "r"(a[3]), "r"(b[0]), "r"(b[1]));
}
// fp16 MMA with fp32 accum (main GEMM)
__device__ __forceinline__ void mma16816_f16(float* c, const uint32_t* a, const uint32_t* b) {
    asm volatile(
        "mma.sync.aligned.m16n8k16.row.col.f32.f16.f16.f32 "
        "{%0,%1,%2,%3}, {%4,%5,%6,%7}, {%8,%9}, {%0,%1,%2,%3};"
        : "+f"(c[0]), "+f"(c[1]), "+f"(c[2]), "+f"(c[3])
        : "r"(a[0]), "r"(a[1]), "r"(a[2]), "r"(a[3]), "r"(b[0]), "r"(b[1]));
}

// ---------------- smem layout for the fused prep+buildw kernel ----------------
#define YPITCH 24     // bf16 units per sY row (48 B)
#define ZPITCH 136    // bf16 units per sZ row (272 B)
#define OPITCH 136    // fp16 units per sO row (272 B)
#define SY_OFF  0          // bf16 [2][128*24]  = 12288 B
#define SZ_OFF  12288      // bf16 [2][16*136]  = 8704 B
#define SB_OFF  20992      // float[128]        = 512 B
#define SZR_OFF 21504      // float[128]        = 512 B
#define SO_OFF  22016      // half [128][136]   = 34816 B
#define BW_SMEM 56832

// ---------------- prep path: fused minmax + quant (CTAs 0..127, all wave-1 resident) ----------------
__device__ __forceinline__ void prep_body(const float* __restrict__ x, char* sm) {
    float* smx = (float*)sm;           // 1024 B
    float* smn = (float*)(sm + 1024);  // 1024 B
    const float4* x4 = (const float4*)x;
    const int tid = threadIdx.x;
    const int base = blockIdx.x * 4096 + tid;

    float mx = -3.4e38f, mn = 3.4e38f;
#pragma unroll
    for (int i = 0; i < 16; i++) {
        float4 v = x4[base + i * 256];
        mx = fmaxf(mx, fmaxf(fmaxf(v.x, v.y), fmaxf(v.z, v.w)));
        mn = fminf(mn, fminf(fminf(v.x, v.y), fminf(v.z, v.w)));
    }
    smx[tid] = mx; smn[tid] = mn;
    __syncthreads();
    for (int s = 128; s > 0; s >>= 1) {
        if (tid < s) { smx[tid] = fmaxf(smx[tid], smx[tid + s]); smn[tid] = fminf(smn[tid], smn[tid + s]); }
        __syncthreads();
    }
    if (tid == 0) {
        g_pmax[blockIdx.x] = smx[0];
        g_pmin[blockIdx.x] = smn[0];
        __threadfence();
        atomicAdd(&g_cnt, 1u);
        while (atomicAdd(&g_cnt, 0u) < PREP_GRID) __nanosleep(64);
    }
    __syncthreads();

    // every prep CTA computes the identical scale from the 128 partials
    if (tid < PREP_GRID) { smx[tid] = g_pmax[tid]; smn[tid] = g_pmin[tid]; }
    __syncthreads();
    for (int s = 64; s > 0; s >>= 1) {
        if (tid < s) { smx[tid] = fmaxf(smx[tid], smx[tid + s]); smn[tid] = fminf(smn[tid], smn[tid + s]); }
        __syncthreads();
    }
    const float scl = fmaxf(__fdiv_rn(smx[0] - smn[0], 254.0f), 1e-8f);   // (max-min)/(2*qmax)
    if (blockIdx.x == 0 && tid == 0) g_scale = scl;

    // phase 2: quantize this CTA's chunk (x is L2-hot from phase 1)
#pragma unroll
    for (int i = 0; i < 16; i++) {
        const int e = base + i * 256;
        float4 v = x4[e];
        float q0 = fminf(fmaxf(rintf(__fdiv_rn(v.x, scl)), -127.f), 127.f);
        float q1 = fminf(fmaxf(rintf(__fdiv_rn(v.y, scl)), -127.f), 127.f);
        float q2 = fminf(fmaxf(rintf(__fdiv_rn(v.z, scl)), -127.f), 127.f);
        float q3 = fminf(fmaxf(rintf(__fdiv_rn(v.w, scl)), -127.f), 127.f);
        union { __half h[4]; uint2 u; } pk;
        pk.h[0] = __float2half_rn(q0);
        pk.h[1] = __float2half_rn(q1);
        pk.h[2] = __float2half_rn(q2);
        pk.h[3] = __float2half_rn(q3);
        ((uint2*)g_q)[e] = pk.u;
    }
    __syncthreads();
    if (tid == 0) {
        unsigned o = atomicAdd(&g_cnt2, 1u);
        if (o == PREP_GRID - 1) { g_cnt = 0; g_cnt2 = 0; }   // reset for next replay
    }
}

// ---------------- buildw path: W tile per (j,k) with tensor cores ----------------
__device__ __forceinline__ void buildw_body(int bid, char* sm,
                                            const float* __restrict__ Ysign,
                                            const float* __restrict__ Zsign,
                                            const float* __restrict__ Yscale,
                                            const float* __restrict__ Zscale,
                                            const float* __restrict__ Aq) {
    __nv_bfloat16* sY0 = (__nv_bfloat16*)(sm + SY_OFF);
    __nv_bfloat16* sY1 = (__nv_bfloat16*)(sm + SY_OFF + MM * YPITCH * 2);
    __nv_bfloat16* sZ0 = (__nv_bfloat16*)(sm + SZ_OFF);
    __nv_bfloat16* sZ1 = (__nv_bfloat16*)(sm + SZ_OFF + LL * ZPITCH * 2);
    float* sB  = (float*)(sm + SB_OFF);
    float* sZr = (float*)(sm + SZR_OFF);
    uint32_t* sO = (uint32_t*)(sm + SO_OFF);   // addressed in uint32 units

    const int j = bid >> 5;
    const int k = bid & 31;
    const int tid = threadIdx.x;
    const int lane = tid & 31;
    const int wid = tid >> 5;

    float ysc[2], zsc[2], a0c[2], a1c[2], a2c[2];
    float a3s = 0.f;
#pragma unroll
    for (int p = 0; p < 2; p++) {
        int idx = (p * JJ + j) * KK + k;
        ysc[p] = Yscale[idx]; zsc[p] = Zscale[idx];
        a0c[p] = Aq[idx * 4 + 0]; a1c[p] = Aq[idx * 4 + 1];
        a2c[p] = Aq[idx * 4 + 2]; a3s += Aq[idx * 4 + 3];
        size_t base = (size_t)idx * (MM * LL);   // 2048 floats (== LL*NN)
        const float4* ys4 = (const float4*)(Ysign + base);
        const float4* zs4 = (const float4*)(Zsign + base);
        __nv_bfloat16* sYp = p ? sY1 : sY0;
        __nv_bfloat16* sZp = p ? sZ1 : sZ0;
#pragma unroll
        for (int i = 0; i < 2; i++) {
            int e4 = tid + i * 256;            // 0..511
            int e = e4 * 4;
            // Y: (m,l) with l fastest, 16 per row
            float4 v = ys4[e4];
            int m = e >> 4, l = e & 15;
            __nv_bfloat162* dy = (__nv_bfloat162*)(&sYp[m * YPITCH + l]);
            dy[0] = __nv_bfloat162{__float2bfloat16(v.x), __float2bfloat16(v.y)};
            dy[1] = __nv_bfloat162{__float2bfloat16(v.z), __float2bfloat16(v.w)};
            // Z: (l,n) with n fastest, 128 per row
            float4 w4 = zs4[e4];
            int zl = e >> 7, n = e & 127;
            __nv_bfloat162* dz = (__nv_bfloat162*)(&sZp[zl * ZPITCH + n]);
            dz[0] = __nv_bfloat162{__float2bfloat16(w4.x), __float2bfloat16(w4.y)};
            dz[1] = __nv_bfloat162{__float2bfloat16(w4.z), __float2bfloat16(w4.w)};
        }
    }
    __syncthreads();

    // row/col sign sums -> coefficient vectors
    if (tid < 128) {
        int m = tid; float s0 = 0.f, s1 = 0.f;
#pragma unroll
        for (int l = 0; l < 16; l++) {
            s0 += __bfloat162float(sY0[m * YPITCH + l]);
            s1 += __bfloat162float(sY1[m * YPITCH + l]);
        }
        sB[m] = a1c[0] * ysc[0] * s0 + a1c[1] * ysc[1] * s1;
    } else {
        int n = tid - 128; float s0 = 0.f, s1 = 0.f;
#pragma unroll
        for (int l = 0; l < 16; l++) {
            s0 += __bfloat162float(sZ0[l * ZPITCH + n]);
            s1 += __bfloat162float(sZ1[l * ZPITCH + n]);
        }
        sZr[n] = a2c[0] * zsc[0] * s0 + a2c[1] * zsc[1] * s1;
    }
    __syncthreads();

    const float c00 = a0c[0] * ysc[0] * zsc[0];
    const float c01 = a0c[1] * ysc[1] * zsc[1];
    const int mb = wid * 16;   // warp's m strip

    // A fragments (16x16, row-major m x l), one per p, loaded once
    uint32_t aoff = (uint32_t)((mb + (lane & 15)) * (YPITCH * 2)) + (uint32_t)((lane >> 4) * 16);
    uint32_t af0[4], af1[4];
    ldsm4(af0, smem_u32(sY0) + aoff);
    ldsm4(af1, smem_u32(sY1) + aoff);

    // B trans-ldsm lane addressing: source rows = l (k dim), cols = n
    uint32_t zoff = (uint32_t)((lane & 15) * (ZPITCH * 2)) + (uint32_t)(((lane >> 4) * 8) * 2);
    const uint32_t zb0 = smem_u32(sZ0) + zoff;
    const uint32_t zb1 = smem_u32(sZ1) + zoff;

    const int r0 = mb + (lane >> 2);
    const int r1 = r0 + 8;
    const float sb0 = sB[r0];
    const float sb1 = sB[r1];
    const int so0 = r0 * (OPITCH / 2);   // uint32 row base
    const int so1 = r1 * (OPITCH / 2);

#pragma unroll
    for (int nc = 0; nc < 4; nc++) {
        const int n0 = nc * 32;
        uint32_t b0a[4], b0b[4], b1a[4], b1b[4];
        ldsm4t(b0a, zb0 + (uint32_t)(n0 * 2));          // p0, n-tiles 0,1
        ldsm4t(b0b, zb0 + (uint32_t)((n0 + 16) * 2));   // p0, n-tiles 2,3
        ldsm4t(b1a, zb1 + (uint32_t)(n0 * 2));
        ldsm4t(b1b, zb1 + (uint32_t)((n0 + 16) * 2));

        float acc0[4][4], acc1[4][4];
#pragma unroll
        for (int t = 0; t < 4; t++)
#pragma unroll
            for (int v = 0; v < 4; v++) { acc0[t][v] = 0.f; acc1[t][v] = 0.f; }

        mma16816_bf(acc0[0], af0, &b0a[0]); mma16816_bf(acc0[1], af0, &b0a[2]);
        mma16816_bf(acc0[2], af0, &b0b[0]); mma16816_bf(acc0[3], af0, &b0b[2]);
        mma16816_bf(acc1[0], af1, &b1a[0]); mma16816_bf(acc1[1], af1, &b1a[2]);
        mma16816_bf(acc1[2], af1, &b1b[0]); mma16816_bf(acc1[3], af1, &b1b[2]);

#pragma unroll
        for (int nt = 0; nt < 4; nt++) {
            const int col = n0 + nt * 8 + (lane & 3) * 2;
            const float2 zr = *(const float2*)(&sZr[col]);
            const float add0 = zr.x + a3s;
            const float add1 = zr.y + a3s;
            float w00 = c00 * acc0[nt][0] + c01 * acc1[nt][0] + sb0 + add0;
            float w01 = c00 * acc0[nt][1] + c01 * acc1[nt][1] + sb0 + add1;
            float w10 = c00 * acc0[nt][2] + c01 * acc1[nt][2] + sb1 + add0;
            float w11 = c00 * acc0[nt][3] + c01 * acc1[nt][3] + sb1 + add1;

            union { __half h[2]; uint32_t u; } pk;
            pk.h[0] = __float2half_rn(w00); pk.h[1] = __float2half_rn(w01);
            sO[so0 + (col >> 1)] = pk.u;
            pk.h[0] = __float2half_rn(w10); pk.h[1] = __float2half_rn(w11);
            sO[so1 + (col >> 1)] = pk.u;
        }
    }
    __syncthreads();

    // coalesced store: 128 rows x 256 B, full 128B lines
    const char* sob = sm + SO_OFF;
    char* gw = (char*)(g_W + (size_t)(j * 128) * KN + k * 128);
#pragma unroll
    for (int it = 0; it < 8; it++) {
        int c = tid + it * 256;         // 0..2047
        int row = c >> 4;
        int seg = c & 15;
        uint4 v = *(const uint4*)(sob + row * (OPITCH * 2) + seg * 16);
        *(uint4*)(gw + (size_t)row * (KN * 2) + seg * 16) = v;
    }
}

// ---------------- fused kernel: prep (CTAs 0..127) + buildw (CTAs 128..1151) ----------------
__global__ void __launch_bounds__(256) k_pb(const float* __restrict__ x,
                                            const float* __restrict__ Ysign,
                                            const float* __restrict__ Zsign,
                                            const float* __restrict__ Yscale,
                                            const float* __restrict__ Zscale,
                                            const float* __restrict__ Aq) {
    extern __shared__ char sm[];
    if (blockIdx.x < PREP_GRID) {
        prep_body(x, sm);
    } else {
        buildw_body(blockIdx.x - PREP_GRID, sm, Ysign, Zsign, Yscale, Zscale, Aq);
    }
}

// ---------------- kernel: warp-MMA GEMM out = act*(q @ W^T) + bias ----------------
// CTA tile 64(b) x 128(jm), 128 threads = 4 warps (2m x 2n), warp tile 32x64.
// Grid 8 x 32 = 256 CTAs; smem 4 x 24KB = 96KB -> 2 CTAs/SM, one wave of 256/296.
// Independent co-resident CTAs hide each other's barrier + ldmatrix latency.
// Stage: A @+0 (8KB), W @+8KB (16KB); 128B rows XOR-swizzled.
__global__ void __launch_bounds__(128, 2) k_gemm(const float* __restrict__ bias,
                                                 float* __restrict__ out) {
    extern __shared__ char smem[];
    const uint32_t sbase = smem_u32(smem);

    const int tid = threadIdx.x;
    const int lane = tid & 31;
    const int wid = tid >> 5;
    const int jt = blockIdx.x;        // jm tile, 0..31
    const int bt = blockIdx.y;        // b tile,  0..7 (64 rows each)
    const int warp_m = wid & 1;       // 0..1 -> m base warp_m*32
    const int warp_n = wid >> 1;      // 0..1 -> n base warp_n*64

    // ---- cp.async source/dest offsets ----
    // A: 64 rows x 128B = 512 x 16B -> 4 per thread; W: 128 rows x 128B = 1024 -> 8 per thread
    uint32_t swoffA[4]; const char* srcq[4];
    uint32_t swoffW[8]; const char* srcw[8];
    {
        const char* gq = (const char*)(g_q + (size_t)(bt * 64) * KN);
        const char* gw = (const char*)(g_W + (size_t)(jt * 128) * KN);
#pragma unroll
        for (int i = 0; i < 4; i++) {
            int idx = tid + i * 128;            // 0..511
            int row = idx >> 3;                 // 0..63
            int seg = (idx & 7) * 16;
            swoffA[i] = (uint32_t)(row * 128) + ((uint32_t)seg ^ (uint32_t)((row & 7) << 4));
            srcq[i] = gq + (size_t)row * (KN * 2) + seg;
        }
#pragma unroll
        for (int i = 0; i < 8; i++) {
            int idx = tid + i * 128;            // 0..1023
            int row = idx >> 3;                 // 0..127
            int seg = (idx & 7) * 16;
            swoffW[i] = (uint32_t)(row * 128) + ((uint32_t)seg ^ (uint32_t)((row & 7) << 4));
            srcw[i] = gw + (size_t)row * (KN * 2) + seg;
        }
    }

    // ---- prefetch chunks 0..2 ----
#pragma unroll
    for (int s = 0; s < NSTG - 1; s++) {
        uint32_t base = sbase + s * STAGE;
        size_t koff = (size_t)s * 128;          // 64 fp16 = 128 bytes
#pragma unroll
        for (int i = 0; i < 4; i++) cp16(base + swoffA[i], srcq[i] + koff);
#pragma unroll
        for (int i = 0; i < 8; i++) cp16(base + 8192 + swoffW[i], srcw[i] + koff);
        CP_COMMIT();
    }

    // ---- ldmatrix lane addressing ----
    const int a_row = warp_m * 32 + (lane & 15);           // + mt*16
    const uint32_t a_hi  = (uint32_t)((lane >> 4) * 16);
    const uint32_t a_swz = (uint32_t)((a_row & 7) << 4);   // invariant under +16
    const int b_g = lane >> 3;                              // 0..3
    const int b_row0 = warp_n * 64 + ((b_g >> 1) << 3) + (lane & 7);  // + i*16
    const uint32_t b_hi  = (uint32_t)((b_g & 1) * 16);
    const uint32_t b_swz = (uint32_t)((b_row0 & 7) << 4);  // invariant under +16

    float acc[2][8][4];
#pragma unroll
    for (int mt = 0; mt < 2; mt++)
#pragma unroll
        for (int nt = 0; nt < 8; nt++)
#pragma unroll
            for (int v = 0; v < 4; v++) acc[mt][nt][v] = 0.f;

    for (int c = 0; c < NCHUNK; c++) {
        CP_WAIT(2);              // chunk c landed (chunks c+1, c+2 may remain)
        __syncthreads();         // all threads see chunk c AND finished compute(c-1)

        // issue chunk c+3 into buffer (c+3)%4 == (c-1)%4, freed by the barrier above
        if (c + 3 < NCHUNK) {
            uint32_t base = sbase + ((c + 3) % NSTG) * STAGE;
            size_t koff = (size_t)(c + 3) * 128;
#pragma unroll
            for (int i = 0; i < 4; i++) cp16(base + swoffA[i], srcq[i] + koff);
#pragma unroll
            for (int i = 0; i < 8; i++) cp16(base + 8192 + swoffW[i], srcw[i] + koff);
        }
        CP_COMMIT();             // fixed group accounting (empty at tail)

        const uint32_t bb = sbase + (c % NSTG) * STAGE;
#pragma unroll
        for (int ks = 0; ks < 4; ks++) {
            uint32_t a[2][4];
#pragma unroll
            for (int mt = 0; mt < 2; mt++)
                ldsm4(a[mt], bb + (uint32_t)((a_row + mt * 16) * 128)
                              + (((uint32_t)(ks * 32) + a_hi) ^ a_swz));
            uint32_t bw[8][2];
#pragma unroll
            for (int i = 0; i < 4; i++) {
                uint32_t ro = (uint32_t)((b_row0 + i * 16) * 128)
                            + (((uint32_t)(ks * 32) + b_hi) ^ b_swz);
                uint32_t r[4];
                ldsm4(r, bb + 8192 + ro);
                bw[2*i][0] = r[0]; bw[2*i][1] = r[1]; bw[2*i+1][0] = r[2]; bw[2*i+1][1] = r[3];
            }
#pragma unroll
            for (int mt = 0; mt < 2; mt++)
#pragma unroll
                for (int nt = 0; nt < 8; nt++)
                    mma16816_f16(acc[mt][nt], a[mt], bw[nt]);
        }
    }

    // ---- epilogue: out = acc*act + bias ----
    const float act = g_scale;
    const int orow0 = bt * 64 + warp_m * 32 + (lane >> 2);
    const int ocol0 = jt * 128 + warp_n * 64 + (lane & 3) * 2;
#pragma unroll
    for (int mt = 0; mt < 2; mt++) {
        const int r0 = orow0 + mt * 16;
#pragma unroll
        for (int nt = 0; nt < 8; nt++) {
            const int col = ocol0 + nt * 8;
            const float2 b2 = *(const float2*)(bias + col);
            float2 v0, v1;
            v0.x = acc[mt][nt][0] * act + b2.x;
            v0.y = acc[mt][nt][1] * act + b2.y;
            v1.x = acc[mt][nt][2] * act + b2.x;
            v1.y = acc[mt][nt][3] * act + b2.y;
            *(float2*)(out + (size_t)r0 * JM + col)       = v0;
            *(float2*)(out + (size_t)(r0 + 8) * JM + col) = v1;
        }
    }
}

// ---------------- launcher ----------------
extern "C" void kernel_launch(void* const* d_in, const int* in_sizes, int n_in,
                              void* d_out, int out_size) {
    const float *x = nullptr, *Ys = nullptr, *Zs = nullptr;
    const float *Ysc = nullptr, *Zsc = nullptr, *A = nullptr, *bias = nullptr;
    for (int i = 0; i < n_in; i++) {
        const int s = in_sizes[i];
        const float* p = (const float*)d_in[i];
        if (s == BATCH * KN && !x) x = p;                                        // 2097152
        else if (s == PP * JJ * KK * MM * LL) { if (!Ys) Ys = p; else Zs = p; }  // 4194304 x2
        else if (s == PP * JJ * KK) { if (!Ysc) Ysc = p; else Zsc = p; }         // 2048 x2
        else if (s == PP * JJ * KK * 4) A = p;                                   // 8192
        else if (s == JM) bias = p;                                              // 4096
    }
    float* out = (float*)d_out;

    cudaFuncSetAttribute(k_pb, cudaFuncAttributeMaxDynamicSharedMemorySize, BW_SMEM);
    k_pb<<<PREP_GRID + JJ * KK, 256, BW_SMEM>>>(x, Ys, Zs, Ysc, Zsc, A);

    const int smem_bytes = NSTG * STAGE;   // 98304
    cudaFuncSetAttribute(k_gemm, cudaFuncAttributeMaxDynamicSharedMemorySize, smem_bytes);
    dim3 grid(JM / 128, BATCH / 64);
    k_gemm<<<grid, 128, smem_bytes>>>(bias, out);
}

// round 13
// speedup vs baseline: 1.2857x; 1.0004x over previous
#include <cuda_runtime.h>
#include <cuda_bf16.h>
#include <cuda_fp16.h>
#include <cstdint>

// ---------------- problem dims ----------------
#define PP 2
#define JJ 32
#define KK 32
#define MM 128
#define LL 16
#define NN 128
#define BATCH 512
#define KN 4096
#define JM 4096
#define BKC 64                 // GEMM K-chunk (fp16 elements)
#define NCHUNK (KN / BKC)      // 64
#define STAGE 24576            // bytes per pipeline stage (A 8KB + W 16KB)
#define NSTG 4
#define PREP_GRID 128

// ---------------- device scratch (no cudaMalloc allowed) ----------------
__device__ float g_pmax[PREP_GRID];
__device__ float g_pmin[PREP_GRID];
__device__ float g_scale;
__device__ unsigned g_cnt  = 0;
__device__ unsigned g_cnt2 = 0;
__device__ __half g_q[(size_t)BATCH * KN];       // quantized activations (exact ints, fp16)
__device__ __half g_W[(size_t)JM * KN];          // fp16 weight matrix

// ---------------- PTX helpers (sm_100-safe only) ----------------
__device__ __forceinline__ uint32_t smem_u32(const void* p) {
    uint32_t a;
    asm("{ .reg .u64 t; cvta.to.shared.u64 t, %1; cvt.u32.u64 %0, t; }" : "=r"(a) : "l"(p));
    return a;
}

__device__ __forceinline__ void cp16(uint32_t dst, const void* src) {
    asm volatile("cp.async.cg.shared.global [%0], [%1], 16;\n" :: "r"(dst), "l"(src));
}
#define CP_COMMIT() asm volatile("cp.async.commit_group;\n" ::: "memory")
#define CP_WAIT(n)  asm volatile("cp.async.wait_group %0;\n" :: "n"(n) : "memory")

__device__ __forceinline__ void ldsm4(uint32_t* r, uint32_t addr) {
    asm volatile("ldmatrix.sync.aligned.m8n8.x4.shared.b16 {%0,%1,%2,%3}, [%4];"
        : "=r"(r[0]), "=r"(r[1]), "=r"(r[2]), "=r"(r[3]) : "r"(addr));
}
__device__ __forceinline__ void ldsm4t(uint32_t* r, uint32_t addr) {
    asm volatile("ldmatrix.sync.aligned.m8n8.x4.trans.shared.b16 {%0,%1,%2,%3}, [%4];"
        : "=r"(r[0]), "=r"(r[1]), "=r"(r[2]), "=r"(r[3]) : "r"(addr));
}

// bf16 MMA (used in buildw where operands are exact small integers)
__device__ __forceinline__ void mma16816_bf(float* c, const uint32_t* a, const uint32_t* b) {
    asm volatile(
        "mma.sync.aligned.m16n8k16.row.col.f32.bf16.bf16.f32 "
        "{%0,%1,%2,%3}, {%4,%5,%6,%7}, {%8,%9}, {%0,%1,%2,%3};"
        : "+f"(c[0]), "+f"(c[1]), "+f"(c[2]), "+f"(c[3])
        : "r"(a[0]), "r"(a[1]), "r"(a[2]), "r"(a[3]), "r"(b[0]), "r"(b[1]));
}
// fp16 MMA with fp32 accum (main GEMM)
__device__ __forceinline__ void mma16816_f16(float* c, const uint32_t* a, const uint32_t* b) {
    asm volatile(
        "mma.sync.aligned.m16n8k16.row.col.f32.f16.f16.f32 "
        "{%0,%1,%2,%3}, {%4,%5,%6,%7}, {%8,%9}, {%0,%1,%2,%3};"
        : "+f"(c[0]), "+f"(c[1]), "+f"(c[2]), "+f"(c[3])
        : "r"(a[0]), "r"(a[1]), "r"(a[2]), "r"(a[3]), "r"(b[0]), "r"(b[1]));
}

// ---------------- smem layout for the fused prep+buildw kernel ----------------
#define YPITCH 24     // bf16 units per sY row (48 B)
#define ZPITCH 136    // bf16 units per sZ row (272 B)
#define OPITCH 136    // fp16 units per sO row (272 B)
#define SY_OFF  0          // bf16 [2][128*24]  = 12288 B
#define SZ_OFF  12288      // bf16 [2][16*136]  = 8704 B
#define SB_OFF  20992      // float[128]        = 512 B
#define SZR_OFF 21504      // float[128]        = 512 B
#define SO_OFF  22016      // half [128][136]   = 34816 B
#define BW_SMEM 56832

// ---------------- prep path: fused minmax + quant (CTAs 0..127, all wave-1 resident) ----------------
__device__ __forceinline__ void prep_body(const float* __restrict__ x, char* sm) {
    float* smx = (float*)sm;           // 1024 B
    float* smn = (float*)(sm + 1024);  // 1024 B
    const float4* x4 = (const float4*)x;
    const int tid = threadIdx.x;
    const int base = blockIdx.x * 4096 + tid;

    float mx = -3.4e38f, mn = 3.4e38f;
#pragma unroll
    for (int i = 0; i < 16; i++) {
        float4 v = x4[base + i * 256];
        mx = fmaxf(mx, fmaxf(fmaxf(v.x, v.y), fmaxf(v.z, v.w)));
        mn = fminf(mn, fminf(fminf(v.x, v.y), fminf(v.z, v.w)));
    }
    smx[tid] = mx; smn[tid] = mn;
    __syncthreads();
    for (int s = 128; s > 0; s >>= 1) {
        if (tid < s) { smx[tid] = fmaxf(smx[tid], smx[tid + s]); smn[tid] = fminf(smn[tid], smn[tid + s]); }
        __syncthreads();
    }
    if (tid == 0) {
        g_pmax[blockIdx.x] = smx[0];
        g_pmin[blockIdx.x] = smn[0];
        __threadfence();
        atomicAdd(&g_cnt, 1u);
        while (atomicAdd(&g_cnt, 0u) < PREP_GRID) __nanosleep(64);
    }
    __syncthreads();

    // every prep CTA computes the identical scale from the 128 partials
    if (tid < PREP_GRID) { smx[tid] = g_pmax[tid]; smn[tid] = g_pmin[tid]; }
    __syncthreads();
    for (int s = 64; s > 0; s >>= 1) {
        if (tid < s) { smx[tid] = fmaxf(smx[tid], smx[tid + s]); smn[tid] = fminf(smn[tid], smn[tid + s]); }
        __syncthreads();
    }
    const float scl = fmaxf(__fdiv_rn(smx[0] - smn[0], 254.0f), 1e-8f);   // (max-min)/(2*qmax)
    if (blockIdx.x == 0 && tid == 0) g_scale = scl;

    // phase 2: quantize this CTA's chunk (x is L2-hot from phase 1)
#pragma unroll
    for (int i = 0; i < 16; i++) {
        const int e = base + i * 256;
        float4 v = x4[e];
        float q0 = fminf(fmaxf(rintf(__fdiv_rn(v.x, scl)), -127.f), 127.f);
        float q1 = fminf(fmaxf(rintf(__fdiv_rn(v.y, scl)), -127.f), 127.f);
        float q2 = fminf(fmaxf(rintf(__fdiv_rn(v.z, scl)), -127.f), 127.f);
        float q3 = fminf(fmaxf(rintf(__fdiv_rn(v.w, scl)), -127.f), 127.f);
        union { __half h[4]; uint2 u; } pk;
        pk.h[0] = __float2half_rn(q0);
        pk.h[1] = __float2half_rn(q1);
        pk.h[2] = __float2half_rn(q2);
        pk.h[3] = __float2half_rn(q3);
        ((uint2*)g_q)[e] = pk.u;
    }
    __syncthreads();
    if (tid == 0) {
        unsigned o = atomicAdd(&g_cnt2, 1u);
        if (o == PREP_GRID - 1) { g_cnt = 0; g_cnt2 = 0; }   // reset for next replay
    }
}

// ---------------- buildw path: W tile per (j,k) with tensor cores ----------------
__device__ __forceinline__ void buildw_body(int bid, char* sm,
                                            const float* __restrict__ Ysign,
                                            const float* __restrict__ Zsign,
                                            const float* __restrict__ Yscale,
                                            const float* __restrict__ Zscale,
                                            const float* __restrict__ Aq) {
    __nv_bfloat16* sY0 = (__nv_bfloat16*)(sm + SY_OFF);
    __nv_bfloat16* sY1 = (__nv_bfloat16*)(sm + SY_OFF + MM * YPITCH * 2);
    __nv_bfloat16* sZ0 = (__nv_bfloat16*)(sm + SZ_OFF);
    __nv_bfloat16* sZ1 = (__nv_bfloat16*)(sm + SZ_OFF + LL * ZPITCH * 2);
    float* sB  = (float*)(sm + SB_OFF);
    float* sZr = (float*)(sm + SZR_OFF);
    uint32_t* sO = (uint32_t*)(sm + SO_OFF);   // addressed in uint32 units

    const int j = bid >> 5;
    const int k = bid & 31;
    const int tid = threadIdx.x;
    const int lane = tid & 31;
    const int wid = tid >> 5;

    float ysc[2], zsc[2], a0c[2], a1c[2], a2c[2];
    float a3s = 0.f;
#pragma unroll
    for (int p = 0; p < 2; p++) {
        int idx = (p * JJ + j) * KK + k;
        ysc[p] = Yscale[idx]; zsc[p] = Zscale[idx];
        a0c[p] = Aq[idx * 4 + 0]; a1c[p] = Aq[idx * 4 + 1];
        a2c[p] = Aq[idx * 4 + 2]; a3s += Aq[idx * 4 + 3];
        size_t base = (size_t)idx * (MM * LL);   // 2048 floats (== LL*NN)
        const float4* ys4 = (const float4*)(Ysign + base);
        const float4* zs4 = (const float4*)(Zsign + base);
        __nv_bfloat16* sYp = p ? sY1 : sY0;
        __nv_bfloat16* sZp = p ? sZ1 : sZ0;
#pragma unroll
        for (int i = 0; i < 2; i++) {
            int e4 = tid + i * 256;            // 0..511
            int e = e4 * 4;
            // Y: (m,l) with l fastest, 16 per row
            float4 v = ys4[e4];
            int m = e >> 4, l = e & 15;
            __nv_bfloat162* dy = (__nv_bfloat162*)(&sYp[m * YPITCH + l]);
            dy[0] = __nv_bfloat162{__float2bfloat16(v.x), __float2bfloat16(v.y)};
            dy[1] = __nv_bfloat162{__float2bfloat16(v.z), __float2bfloat16(v.w)};
            // Z: (l,n) with n fastest, 128 per row
            float4 w4 = zs4[e4];
            int zl = e >> 7, n = e & 127;
            __nv_bfloat162* dz = (__nv_bfloat162*)(&sZp[zl * ZPITCH + n]);
            dz[0] = __nv_bfloat162{__float2bfloat16(w4.x), __float2bfloat16(w4.y)};
            dz[1] = __nv_bfloat162{__float2bfloat16(w4.z), __float2bfloat16(w4.w)};
        }
    }
    __syncthreads();

    // row/col sign sums -> coefficient vectors
    if (tid < 128) {
        int m = tid; float s0 = 0.f, s1 = 0.f;
#pragma unroll
        for (int l = 0; l < 16; l++) {
            s0 += __bfloat162float(sY0[m * YPITCH + l]);
            s1 += __bfloat162float(sY1[m * YPITCH + l]);
        }
        sB[m] = a1c[0] * ysc[0] * s0 + a1c[1] * ysc[1] * s1;
    } else {
        int n = tid - 128; float s0 = 0.f, s1 = 0.f;
#pragma unroll
        for (int l = 0; l < 16; l++) {
            s0 += __bfloat162float(sZ0[l * ZPITCH + n]);
            s1 += __bfloat162float(sZ1[l * ZPITCH + n]);
        }
        sZr[n] = a2c[0] * zsc[0] * s0 + a2c[1] * zsc[1] * s1;
    }
    __syncthreads();

    const float c00 = a0c[0] * ysc[0] * zsc[0];
    const float c01 = a0c[1] * ysc[1] * zsc[1];
    const int mb = wid * 16;   // warp's m strip

    // A fragments (16x16, row-major m x l), one per p, loaded once
    uint32_t aoff = (uint32_t)((mb + (lane & 15)) * (YPITCH * 2)) + (uint32_t)((lane >> 4) * 16);
    uint32_t af0[4], af1[4];
    ldsm4(af0, smem_u32(sY0) + aoff);
    ldsm4(af1, smem_u32(sY1) + aoff);

    // B trans-ldsm lane addressing: source rows = l (k dim), cols = n
    uint32_t zoff = (uint32_t)((lane & 15) * (ZPITCH * 2)) + (uint32_t)(((lane >> 4) * 8) * 2);
    const uint32_t zb0 = smem_u32(sZ0) + zoff;
    const uint32_t zb1 = smem_u32(sZ1) + zoff;

    const int r0 = mb + (lane >> 2);
    const int r1 = r0 + 8;
    const float sb0 = sB[r0];
    const float sb1 = sB[r1];
    const int so0 = r0 * (OPITCH / 2);   // uint32 row base
    const int so1 = r1 * (OPITCH / 2);

#pragma unroll
    for (int nc = 0; nc < 4; nc++) {
        const int n0 = nc * 32;
        uint32_t b0a[4], b0b[4], b1a[4], b1b[4];
        ldsm4t(b0a, zb0 + (uint32_t)(n0 * 2));          // p0, n-tiles 0,1
        ldsm4t(b0b, zb0 + (uint32_t)((n0 + 16) * 2));   // p0, n-tiles 2,3
        ldsm4t(b1a, zb1 + (uint32_t)(n0 * 2));
        ldsm4t(b1b, zb1 + (uint32_t)((n0 + 16) * 2));

        float acc0[4][4], acc1[4][4];
#pragma unroll
        for (int t = 0; t < 4; t++)
#pragma unroll
            for (int v = 0; v < 4; v++) { acc0[t][v] = 0.f; acc1[t][v] = 0.f; }

        mma16816_bf(acc0[0], af0, &b0a[0]); mma16816_bf(acc0[1], af0, &b0a[2]);
        mma16816_bf(acc0[2], af0, &b0b[0]); mma16816_bf(acc0[3], af0, &b0b[2]);
        mma16816_bf(acc1[0], af1, &b1a[0]); mma16816_bf(acc1[1], af1, &b1a[2]);
        mma16816_bf(acc1[2], af1, &b1b[0]); mma16816_bf(acc1[3], af1, &b1b[2]);

#pragma unroll
        for (int nt = 0; nt < 4; nt++) {
            const int col = n0 + nt * 8 + (lane & 3) * 2;
            const float2 zr = *(const float2*)(&sZr[col]);
            const float add0 = zr.x + a3s;
            const float add1 = zr.y + a3s;
            float w00 = c00 * acc0[nt][0] + c01 * acc1[nt][0] + sb0 + add0;
            float w01 = c00 * acc0[nt][1] + c01 * acc1[nt][1] + sb0 + add1;
            float w10 = c00 * acc0[nt][2] + c01 * acc1[nt][2] + sb1 + add0;
            float w11 = c00 * acc0[nt][3] + c01 * acc1[nt][3] + sb1 + add1;

            union { __half h[2]; uint32_t u; } pk;
            pk.h[0] = __float2half_rn(w00); pk.h[1] = __float2half_rn(w01);
            sO[so0 + (col >> 1)] = pk.u;
            pk.h[0] = __float2half_rn(w10); pk.h[1] = __float2half_rn(w11);
            sO[so1 + (col >> 1)] = pk.u;
        }
    }
    __syncthreads();

    // coalesced store: 128 rows x 256 B, full 128B lines
    const char* sob = sm + SO_OFF;
    char* gw = (char*)(g_W + (size_t)(j * 128) * KN + k * 128);
#pragma unroll
    for (int it = 0; it < 8; it++) {
        int c = tid + it * 256;         // 0..2047
        int row = c >> 4;
        int seg = c & 15;
        uint4 v = *(const uint4*)(sob + row * (OPITCH * 2) + seg * 16);
        *(uint4*)(gw + (size_t)row * (KN * 2) + seg * 16) = v;
    }
}

// ---------------- fused kernel: prep (CTAs 0..127) + buildw (CTAs 128..1151) ----------------
__global__ void __launch_bounds__(256) k_pb(const float* __restrict__ x,
                                            const float* __restrict__ Ysign,
                                            const float* __restrict__ Zsign,
                                            const float* __restrict__ Yscale,
                                            const float* __restrict__ Zscale,
                                            const float* __restrict__ Aq) {
    extern __shared__ char sm[];
    if (blockIdx.x < PREP_GRID) {
        prep_body(x, sm);
    } else {
        buildw_body(blockIdx.x - PREP_GRID, sm, Ysign, Zsign, Yscale, Zscale, Aq);
    }
}

// ---------------- kernel: warp-MMA GEMM out = act*(q @ W^T) + bias ----------------
// CTA tile 64(b) x 128(jm), 128 threads = 4 warps (2m x 2n), warp tile 32x64.
// Grid 8 x 32 = 256 CTAs; smem 4 x 24KB = 96KB -> 2 CTAs/SM.
// Register-double-buffered fragments: ldsm(ks+1) issued before mma(ks) so the
// volatile-asm stream never stalls an MMA on a just-issued ldmatrix.
__global__ void __launch_bounds__(128, 2) k_gemm(const float* __restrict__ bias,
                                                 float* __restrict__ out) {
    extern __shared__ char smem[];
    const uint32_t sbase = smem_u32(smem);

    const int tid = threadIdx.x;
    const int lane = tid & 31;
    const int wid = tid >> 5;
    const int jt = blockIdx.x;        // jm tile, 0..31
    const int bt = blockIdx.y;        // b tile,  0..7 (64 rows each)
    const int warp_m = wid & 1;       // 0..1 -> m base warp_m*32
    const int warp_n = wid >> 1;      // 0..1 -> n base warp_n*64

    // ---- cp.async source/dest offsets ----
    uint32_t swoffA[4]; const char* srcq[4];
    uint32_t swoffW[8]; const char* srcw[8];
    {
        const char* gq = (const char*)(g_q + (size_t)(bt * 64) * KN);
        const char* gw = (const char*)(g_W + (size_t)(jt * 128) * KN);
#pragma unroll
        for (int i = 0; i < 4; i++) {
            int idx = tid + i * 128;            // 0..511
            int row = idx >> 3;                 // 0..63
            int seg = (idx & 7) * 16;
            swoffA[i] = (uint32_t)(row * 128) + ((uint32_t)seg ^ (uint32_t)((row & 7) << 4));
            srcq[i] = gq + (size_t)row * (KN * 2) + seg;
        }
#pragma unroll
        for (int i = 0; i < 8; i++) {
            int idx = tid + i * 128;            // 0..1023
            int row = idx >> 3;                 // 0..127
            int seg = (idx & 7) * 16;
            swoffW[i] = (uint32_t)(row * 128) + ((uint32_t)seg ^ (uint32_t)((row & 7) << 4));
            srcw[i] = gw + (size_t)row * (KN * 2) + seg;
        }
    }

    // ---- prefetch chunks 0..2 ----
#pragma unroll
    for (int s = 0; s < NSTG - 1; s++) {
        uint32_t base = sbase + s * STAGE;
        size_t koff = (size_t)s * 128;          // 64 fp16 = 128 bytes
#pragma unroll
        for (int i = 0; i < 4; i++) cp16(base + swoffA[i], srcq[i] + koff);
#pragma unroll
        for (int i = 0; i < 8; i++) cp16(base + 8192 + swoffW[i], srcw[i] + koff);
        CP_COMMIT();
    }

    // ---- ldmatrix lane addressing ----
    const int a_row = warp_m * 32 + (lane & 15);           // + mt*16
    const uint32_t a_hi  = (uint32_t)((lane >> 4) * 16);
    const uint32_t a_swz = (uint32_t)((a_row & 7) << 4);   // invariant under +16
    const int b_g = lane >> 3;                              // 0..3
    const int b_row0 = warp_n * 64 + ((b_g >> 1) << 3) + (lane & 7);  // + i*16
    const uint32_t b_hi  = (uint32_t)((b_g & 1) * 16);
    const uint32_t b_swz = (uint32_t)((b_row0 & 7) << 4);  // invariant under +16

    float acc[2][8][4];
#pragma unroll
    for (int mt = 0; mt < 2; mt++)
#pragma unroll
        for (int nt = 0; nt < 8; nt++)
#pragma unroll
            for (int v = 0; v < 4; v++) acc[mt][nt][v] = 0.f;

    // register-double-buffered fragments
    uint32_t a_fr[2][2][4];   // [buf][mt][4]
    uint32_t b_fr[2][8][2];   // [buf][nt][2]

    for (int c = 0; c < NCHUNK; c++) {
        CP_WAIT(2);              // chunk c landed (chunks c+1, c+2 may remain)
        __syncthreads();         // all threads see chunk c AND finished compute(c-1)

        // issue chunk c+3 into buffer (c+3)%4 == (c-1)%4, freed by the barrier above
        if (c + 3 < NCHUNK) {
            uint32_t base = sbase + ((c + 3) % NSTG) * STAGE;
            size_t koff = (size_t)(c + 3) * 128;
#pragma unroll
            for (int i = 0; i < 4; i++) cp16(base + swoffA[i], srcq[i] + koff);
#pragma unroll
            for (int i = 0; i < 8; i++) cp16(base + 8192 + swoffW[i], srcw[i] + koff);
        }
        CP_COMMIT();             // fixed group accounting (empty at tail)

        const uint32_t bb = sbase + (c % NSTG) * STAGE;

        // load ks=0 fragments into buf 0
#pragma unroll
        for (int mt = 0; mt < 2; mt++)
            ldsm4(a_fr[0][mt], bb + (uint32_t)((a_row + mt * 16) * 128) + (a_hi ^ a_swz));
#pragma unroll
        for (int i = 0; i < 4; i++) {
            uint32_t ro = (uint32_t)((b_row0 + i * 16) * 128) + (b_hi ^ b_swz);
            uint32_t r[4];
            ldsm4(r, bb + 8192 + ro);
            b_fr[0][2*i][0] = r[0]; b_fr[0][2*i][1] = r[1];
            b_fr[0][2*i+1][0] = r[2]; b_fr[0][2*i+1][1] = r[3];
        }

#pragma unroll
        for (int ks = 0; ks < 4; ks++) {
            const int cur = ks & 1;
            const int nxt = cur ^ 1;
            if (ks < 3) {
                const uint32_t kso = (uint32_t)((ks + 1) * 32);
#pragma unroll
                for (int mt = 0; mt < 2; mt++)
                    ldsm4(a_fr[nxt][mt], bb + (uint32_t)((a_row + mt * 16) * 128)
                                          + ((kso + a_hi) ^ a_swz));
#pragma unroll
                for (int i = 0; i < 4; i++) {
                    uint32_t ro = (uint32_t)((b_row0 + i * 16) * 128)
                                + ((kso + b_hi) ^ b_swz);
                    uint32_t r[4];
                    ldsm4(r, bb + 8192 + ro);
                    b_fr[nxt][2*i][0] = r[0]; b_fr[nxt][2*i][1] = r[1];
                    b_fr[nxt][2*i+1][0] = r[2]; b_fr[nxt][2*i+1][1] = r[3];
                }
            }
#pragma unroll
            for (int mt = 0; mt < 2; mt++)
#pragma unroll
                for (int nt = 0; nt < 8; nt++)
                    mma16816_f16(acc[mt][nt], a_fr[cur][mt], b_fr[cur][nt]);
        }
    }

    // ---- epilogue: out = acc*act + bias ----
    const float act = g_scale;
    const int orow0 = bt * 64 + warp_m * 32 + (lane >> 2);
    const int ocol0 = jt * 128 + warp_n * 64 + (lane & 3) * 2;
#pragma unroll
    for (int mt = 0; mt < 2; mt++) {
        const int r0 = orow0 + mt * 16;
#pragma unroll
        for (int nt = 0; nt < 8; nt++) {
            const int col = ocol0 + nt * 8;
            const float2 b2 = *(const float2*)(bias + col);
            float2 v0, v1;
            v0.x = acc[mt][nt][0] * act + b2.x;
            v0.y = acc[mt][nt][1] * act + b2.y;
            v1.x = acc[mt][nt][2] * act + b2.x;
            v1.y = acc[mt][nt][3] * act + b2.y;
            *(float2*)(out + (size_t)r0 * JM + col)       = v0;
            *(float2*)(out + (size_t)(r0 + 8) * JM + col) = v1;
        }
    }
}

// ---------------- launcher ----------------
extern "C" void kernel_launch(void* const* d_in, const int* in_sizes, int n_in,
                              void* d_out, int out_size) {
    const float *x = nullptr, *Ys = nullptr, *Zs = nullptr;
    const float *Ysc = nullptr, *Zsc = nullptr, *A = nullptr, *bias = nullptr;
    for (int i = 0; i < n_in; i++) {
        const int s = in_sizes[i];
        const float* p = (const float*)d_in[i];
        if (s == BATCH * KN && !x) x = p;                                        // 2097152
        else if (s == PP * JJ * KK * MM * LL) { if (!Ys) Ys = p; else Zs = p; }  // 4194304 x2
        else if (s == PP * JJ * KK) { if (!Ysc) Ysc = p; else Zsc = p; }         // 2048 x2
        else if (s == PP * JJ * KK * 4) A = p;                                   // 8192
        else if (s == JM) bias = p;                                              // 4096
    }
    float* out = (float*)d_out;

    cudaFuncSetAttribute(k_pb, cudaFuncAttributeMaxDynamicSharedMemorySize, BW_SMEM);
    k_pb<<<PREP_GRID + JJ * KK, 256, BW_SMEM>>>(x, Ys, Zs, Ysc, Zsc, A);

    const int smem_bytes = NSTG * STAGE;   // 98304
    cudaFuncSetAttribute(k_gemm, cudaFuncAttributeMaxDynamicSharedMemorySize, smem_bytes);
    dim3 grid(JM / 128, BATCH / 64);
    k_gemm<<<grid, 128, smem_bytes>>>(bias, out);
}